// round 12
// baseline (speedup 1.0000x reference)
#include <cuda_runtime.h>
#include <cuda_fp16.h>
#include <cstdint>

#define NN 50000
#define EE 600000
#define ET (EE + NN)
#define SCAN_B 1024
#define NBLK ((NN + SCAN_B - 1) / SCAN_B)

// ---------------- scratch ---------------------------------------------------------
__device__ __half g_ahi[(size_t)NN * 256];      // layer input (fp16)
__device__ __half g_hhi[(size_t)NN * 256];      // GEMM output hi
__device__ __half g_w0hi[256 * 256], g_w0lo[256 * 256];
__device__ __half g_w1hi[256 * 256], g_w1lo[256 * 256];
__device__ __half g_w2hi[64 * 256],  g_w2lo[64 * 256];
__device__ float g_as[NN * 4];
__device__ float g_ad[NN * 4];
__device__ int   g_cnt[NN];
__device__ int   g_incl[NBLK * SCAN_B];
__device__ int   g_bsum[NBLK];
__device__ int   g_rowptr[NN + 1];
__device__ int   g_fill[NN];
__device__ int   g_col[ET];

// ---------------- PTX helpers -----------------------------------------------------
__device__ __forceinline__ uint32_t smem_u32(const void* p) {
    uint32_t a;
    asm("{ .reg .u64 t; cvta.to.shared.u64 t, %1; cvt.u32.u64 %0, t; }" : "=r"(a) : "l"(p));
    return a;
}
__device__ __forceinline__ void cp_async16(uint32_t dst, const void* src) {
    asm volatile("cp.async.cg.shared.global [%0], [%1], 16;"
                 :: "r"(dst), "l"(__cvta_generic_to_global(src)) : "memory");
}
__device__ __forceinline__ void ldsm_x4(uint32_t& r0, uint32_t& r1, uint32_t& r2,
                                        uint32_t& r3, uint32_t addr) {
    asm volatile("ldmatrix.sync.aligned.m8n8.x4.shared.b16 {%0,%1,%2,%3}, [%4];"
                 : "=r"(r0), "=r"(r1), "=r"(r2), "=r"(r3) : "r"(addr));
}
__device__ __forceinline__ void mma16816(float* c, const uint32_t* a, const uint32_t* b) {
    asm volatile("mma.sync.aligned.m16n8k16.row.col.f32.f16.f16.f32 "
                 "{%0,%1,%2,%3}, {%4,%5,%6,%7}, {%8,%9}, {%0,%1,%2,%3};"
                 : "+f"(c[0]), "+f"(c[1]), "+f"(c[2]), "+f"(c[3])
                 : "r"(a[0]), "r"(a[1]), "r"(a[2]), "r"(a[3]), "r"(b[0]), "r"(b[1]));
}
#define SW128(o) ((o) ^ (((o) >> 3) & 0x70))

__device__ __forceinline__ void split2(float v, __half& hi, __half& lo) {
    hi = __float2half_rn(v);
    lo = __float2half_rn(v - __half2float(hi));
}

// ---------------- conversions -----------------------------------------------------
__global__ void k_tofp16_x(const float* __restrict__ x) {
    int i = blockIdx.x * blockDim.x + threadIdx.x;
    if (i >= NN * 64) return;
    float4 v = ((const float4*)x)[i];
    ((__half2*)g_ahi)[2 * i]     = __floats2half2_rn(v.x, v.y);
    ((__half2*)g_ahi)[2 * i + 1] = __floats2half2_rn(v.z, v.w);
}

template <int NO>
__global__ void k_split_wt(const float* __restrict__ W, __half* __restrict__ hi,
                           __half* __restrict__ lo) {
    int i = blockIdx.x * blockDim.x + threadIdx.x;
    if (i >= 256 * NO) return;
    int k = i / NO, n = i % NO;
    __half h, l;
    split2(W[i], h, l);
    hi[n * 256 + k] = h;
    lo[n * 256 + k] = l;
}

// ---------------- GEMM: 8 warps, A fp16, B hi/lo (2 passes), fused alpha ----------
template <int NO>
__global__ __launch_bounds__(256, 2) void k_gemm_mma(const __half* __restrict__ A,
                                                     const __half* __restrict__ Bhi,
                                                     const __half* __restrict__ Blo,
                                                     __half* __restrict__ Hhi,
                                                     const float* __restrict__ a_s,
                                                     const float* __restrict__ a_d) {
    constexpr int BM = 128, BN = (NO == 256) ? 128 : 64;
    constexpr int WN = BN / 2;
    constexpr int NG = WN / 8;
    constexpr int ASZ = 128 * 128;
    constexpr int BSZ = BN * 128;
    constexpr int STG = ASZ + 2 * BSZ;

    extern __shared__ __align__(1024) char smraw[];
    const uint32_t sb = smem_u32(smraw);
    const int tid = threadIdx.x, w = tid >> 5, lane = tid & 31;
    const int wm = w & 3, wn = w >> 2;
    const int bm = blockIdx.y * BM, bn = blockIdx.x * BN;

    auto load = [&](int c) {
        const uint32_t st = sb + (c & 1) * STG;
        const int ko = c * 64;
        for (int t = tid; t < 128 * 8; t += 256) {
            int r = t >> 3, q = t & 7;
            int gr = bm + r; if (gr >= NN) gr = NN - 1;
            cp_async16(st + SW128(r * 128 + q * 16), A + (size_t)gr * 256 + ko + q * 8);
        }
        for (int t = tid; t < BN * 8; t += 256) {
            int r = t >> 3, q = t & 7;
            size_t go = (size_t)(bn + r) * 256 + ko + q * 8;
            uint32_t so = SW128(r * 128 + q * 16);
            cp_async16(st + ASZ + so, Bhi + go);
            cp_async16(st + ASZ + BSZ + so, Blo + go);
        }
        asm volatile("cp.async.commit_group;" ::: "memory");
    };

    load(0);
    load(1);

    float acc[2][NG][4] = {};
    const int a_row = wm * 32 + (lane & 15);
    const int a_colq = (lane >> 4) * 16;
    const int b_row = wn * WN + (lane >> 4) * 8 + (lane & 7);
    const int b_colq = ((lane >> 3) & 1) * 16;

    for (int c = 0; c < 4; ++c) {
        const uint32_t st = sb + (c & 1) * STG;
        if (c < 3) asm volatile("cp.async.wait_group 1;" ::: "memory");
        else       asm volatile("cp.async.wait_group 0;" ::: "memory");
        __syncthreads();
#pragma unroll
        for (int kk = 0; kk < 4; ++kk) {
            uint32_t ah[8], bb[2 * NG];
#pragma unroll
            for (int f = 0; f < 2; ++f)
                ldsm_x4(ah[f * 4], ah[f * 4 + 1], ah[f * 4 + 2], ah[f * 4 + 3],
                        st + SW128((a_row + f * 16) * 128 + kk * 32 + a_colq));
#pragma unroll
            for (int g2 = 0; g2 < NG / 2; ++g2)
                ldsm_x4(bb[g2 * 4], bb[g2 * 4 + 1], bb[g2 * 4 + 2], bb[g2 * 4 + 3],
                        st + ASZ + SW128((b_row + g2 * 16) * 128 + kk * 32 + b_colq));
#pragma unroll
            for (int f = 0; f < 2; ++f)
#pragma unroll
                for (int g = 0; g < NG; ++g)
                    mma16816(acc[f][g], ah + f * 4, bb + g * 2);
#pragma unroll
            for (int g2 = 0; g2 < NG / 2; ++g2)
                ldsm_x4(bb[g2 * 4], bb[g2 * 4 + 1], bb[g2 * 4 + 2], bb[g2 * 4 + 3],
                        st + ASZ + BSZ + SW128((b_row + g2 * 16) * 128 + kk * 32 + b_colq));
#pragma unroll
            for (int f = 0; f < 2; ++f)
#pragma unroll
                for (int g = 0; g < NG; ++g)
                    mma16816(acc[f][g], ah + f * 4, bb + g * 2);
        }
        __syncthreads();
        if (c + 2 < 4) load(c + 2);
    }

    if constexpr (NO == 256) {
        const int head = blockIdx.x * 2 + wn;
        float as_r[2 * NG], ad_r[2 * NG];
#pragma unroll
        for (int g = 0; g < NG; ++g) {
            int cl = head * 64 + g * 8 + (lane & 3) * 2;
            as_r[g * 2] = a_s[cl];     as_r[g * 2 + 1] = a_s[cl + 1];
            ad_r[g * 2] = a_d[cl];     ad_r[g * 2 + 1] = a_d[cl + 1];
        }
#pragma unroll
        for (int f = 0; f < 2; ++f) {
#pragma unroll
            for (int rr = 0; rr < 2; ++rr) {
                float ps = 0.f, pd = 0.f;
#pragma unroll
                for (int g = 0; g < NG; ++g) {
                    float c0 = acc[f][g][rr * 2], c1 = acc[f][g][rr * 2 + 1];
                    ps += c0 * as_r[g * 2] + c1 * as_r[g * 2 + 1];
                    pd += c0 * ad_r[g * 2] + c1 * ad_r[g * 2 + 1];
                }
                ps += __shfl_xor_sync(0xffffffffu, ps, 1);
                ps += __shfl_xor_sync(0xffffffffu, ps, 2);
                pd += __shfl_xor_sync(0xffffffffu, pd, 1);
                pd += __shfl_xor_sync(0xffffffffu, pd, 2);
                int m = bm + wm * 32 + f * 16 + rr * 8 + (lane >> 2);
                if ((lane & 3) == 0 && m < NN) {
                    g_as[m * 4 + head] = ps;
                    g_ad[m * 4 + head] = pd;
                }
            }
        }
#pragma unroll
        for (int f = 0; f < 2; ++f) {
#pragma unroll
            for (int g = 0; g < NG; ++g) {
                int m = bm + wm * 32 + f * 16 + (lane >> 2);
                int n = bn + wn * 64 + g * 8 + (lane & 3) * 2;
#pragma unroll
                for (int rr = 0; rr < 2; ++rr) {
                    int mm = m + rr * 8;
                    if (mm < NN)
                        *(__half2*)(Hhi + (size_t)mm * NO + n) =
                            __floats2half2_rn(acc[f][g][rr * 2], acc[f][g][rr * 2 + 1]);
                }
            }
        }
    } else {
        // store Hhi
#pragma unroll
        for (int f = 0; f < 2; ++f) {
#pragma unroll
            for (int g = 0; g < NG; ++g) {
                int m = bm + wm * 32 + f * 16 + (lane >> 2);
                int n = bn + wn * WN + g * 8 + (lane & 3) * 2;
#pragma unroll
                for (int rr = 0; rr < 2; ++rr) {
                    int mm = m + rr * 8;
                    if (mm < NN)
                        *(__half2*)(Hhi + (size_t)mm * NO + n) =
                            __floats2half2_rn(acc[f][g][rr * 2], acc[f][g][rr * 2 + 1]);
                }
            }
        }
        // fused alpha (H=1): cross-warp (wn 0/1) reduction via reused tile smem
        float as_r[2 * NG], ad_r[2 * NG];
#pragma unroll
        for (int g = 0; g < NG; ++g) {
            int cl = wn * 32 + g * 8 + (lane & 3) * 2;
            as_r[g * 2] = a_s[cl];     as_r[g * 2 + 1] = a_s[cl + 1];
            ad_r[g * 2] = a_d[cl];     ad_r[g * 2 + 1] = a_d[cl + 1];
        }
        float psv[2][2], pdv[2][2];
#pragma unroll
        for (int f = 0; f < 2; ++f) {
#pragma unroll
            for (int rr = 0; rr < 2; ++rr) {
                float ps = 0.f, pd = 0.f;
#pragma unroll
                for (int g = 0; g < NG; ++g) {
                    float c0 = acc[f][g][rr * 2], c1 = acc[f][g][rr * 2 + 1];
                    ps += c0 * as_r[g * 2] + c1 * as_r[g * 2 + 1];
                    pd += c0 * ad_r[g * 2] + c1 * ad_r[g * 2 + 1];
                }
                ps += __shfl_xor_sync(0xffffffffu, ps, 1);
                ps += __shfl_xor_sync(0xffffffffu, ps, 2);
                pd += __shfl_xor_sync(0xffffffffu, pd, 1);
                pd += __shfl_xor_sync(0xffffffffu, pd, 2);
                psv[f][rr] = ps; pdv[f][rr] = pd;
            }
        }
        float* red = (float*)smraw;
        if (wn == 0 && (lane & 3) == 0) {
#pragma unroll
            for (int f = 0; f < 2; ++f)
#pragma unroll
                for (int rr = 0; rr < 2; ++rr) {
                    int row = wm * 32 + f * 16 + rr * 8 + (lane >> 2);
                    red[row] = psv[f][rr];
                    red[128 + row] = pdv[f][rr];
                }
        }
        __syncthreads();
        if (wn == 1 && (lane & 3) == 0) {
#pragma unroll
            for (int f = 0; f < 2; ++f)
#pragma unroll
                for (int rr = 0; rr < 2; ++rr) {
                    int row = wm * 32 + f * 16 + rr * 8 + (lane >> 2);
                    int m = bm + row;
                    if (m < NN) {
                        g_as[m] = red[row] + psv[f][rr];
                        g_ad[m] = red[128 + row] + pdv[f][rr];
                    }
                }
        }
    }
}

// ---------------- CSR build -------------------------------------------------------
__global__ void k_zero_cnt() {
    int i = blockIdx.x * blockDim.x + threadIdx.x;
    if (i < NN) g_cnt[i] = 0;
}
__global__ void k_count(const int* __restrict__ ei) {
    int e = blockIdx.x * blockDim.x + threadIdx.x;
    if (e >= ET) return;
    int d = (e < EE) ? ei[EE + e] : (e - EE);
    atomicAdd(&g_cnt[d], 1);
}
__global__ void k_scan1() {
    __shared__ int sh[SCAN_B];
    int tid = threadIdx.x;
    int i = blockIdx.x * SCAN_B + tid;
    int v = (i < NN) ? g_cnt[i] : 0;
    sh[tid] = v;
    __syncthreads();
    for (int off = 1; off < SCAN_B; off <<= 1) {
        int t = (tid >= off) ? sh[tid - off] : 0;
        __syncthreads();
        sh[tid] += t;
        __syncthreads();
    }
    g_incl[i] = sh[tid];
    if (tid == SCAN_B - 1) g_bsum[blockIdx.x] = sh[tid];
}
__global__ void k_scan2() {
    if (threadIdx.x == 0) {
        int s = 0;
        for (int i = 0; i < NBLK; ++i) { int t = g_bsum[i]; g_bsum[i] = s; s += t; }
    }
}
__global__ void k_scan3() {
    int i = blockIdx.x * blockDim.x + threadIdx.x;
    if (i < NN) {
        int v = g_cnt[i];
        int ex = g_incl[i] - v + g_bsum[i >> 10];
        g_rowptr[i] = ex;
        g_fill[i] = ex;
    }
    if (i == 0) g_rowptr[NN] = ET;
}
__global__ void k_fill(const int* __restrict__ ei) {
    int e = blockIdx.x * blockDim.x + threadIdx.x;
    if (e >= ET) return;
    int s, d;
    if (e < EE) { s = ei[e]; d = ei[EE + e]; }
    else        { s = e - EE; d = s; }
    int pos = atomicAdd(&g_fill[d], 1);
    g_col[pos] = s;
}

// ---------------- conv for H=4 layers: TWO warps per node (heads split) -----------
template <bool RELU>
__global__ __launch_bounds__(256) void k_conv4(const float* __restrict__ as_,
                                               const float* __restrict__ ad_,
                                               const float* __restrict__ bias,
                                               __half* __restrict__ ohi) {
    int gw = (blockIdx.x * blockDim.x + threadIdx.x) >> 5;
    int lane = threadIdx.x & 31;
    int node = gw >> 1, sub = gw & 1;        // sub owns heads 2sub..2sub+1, ch sub*128..
    if (node >= NN) return;
    int beg = g_rowptr[node], end = g_rowptr[node + 1];

    float adh0 = ad_[node * 4 + sub * 2];
    float adh1 = ad_[node * 4 + sub * 2 + 1];

    // stats pass: online softmax for this warp's 2 heads
    float mx0 = -1e30f, mx1 = -1e30f, sm0 = 0.f, sm1 = 0.f;
    for (int i = beg + lane; i < end; i += 32) {
        int s = g_col[i];
        float2 a2 = *(const float2*)(as_ + s * 4 + sub * 2);
        float e0 = a2.x + adh0; e0 = e0 > 0.f ? e0 : 0.2f * e0;
        float e1 = a2.y + adh1; e1 = e1 > 0.f ? e1 : 0.2f * e1;
        if (e0 > mx0) { sm0 = sm0 * __expf(mx0 - e0) + 1.f; mx0 = e0; }
        else          { sm0 += __expf(e0 - mx0); }
        if (e1 > mx1) { sm1 = sm1 * __expf(mx1 - e1) + 1.f; mx1 = e1; }
        else          { sm1 += __expf(e1 - mx1); }
    }
#pragma unroll
    for (int o = 16; o; o >>= 1) {
        float mo = __shfl_xor_sync(0xffffffffu, mx0, o);
        float so = __shfl_xor_sync(0xffffffffu, sm0, o);
        float mn = fmaxf(mx0, mo);
        sm0 = sm0 * __expf(mx0 - mn) + so * __expf(mo - mn);
        mx0 = mn;
        mo = __shfl_xor_sync(0xffffffffu, mx1, o);
        so = __shfl_xor_sync(0xffffffffu, sm1, o);
        mn = fmaxf(mx1, mo);
        sm1 = sm1 * __expf(mx1 - mn) + so * __expf(mo - mn);
        mx1 = mn;
    }

    // gather: lane owns 4 channels; lanes 0-15 -> local head 0, 16-31 -> head 1
    const int hl = lane >> 4;
    const int myh = sub * 2 + hl;
    const float mm = hl ? mx1 : mx0;
    const float inv = 1.f / (hl ? sm1 : sm0);
    const float adm = hl ? adh1 : adh0;
    float acc0 = 0.f, acc1 = 0.f, acc2 = 0.f, acc3 = 0.f;
#pragma unroll 4
    for (int i = beg; i < end; ++i) {
        int s = g_col[i];
        float e = as_[s * 4 + myh] + adm;
        e = e > 0.f ? e : 0.2f * e;
        float w = __expf(e - mm) * inv;
        uint2 raw = *(const uint2*)(g_hhi + (size_t)s * 256 + sub * 128 + lane * 4);
        float2 f0 = __half22float2(*(__half2*)&raw.x);
        float2 f1 = __half22float2(*(__half2*)&raw.y);
        acc0 += w * f0.x; acc1 += w * f0.y; acc2 += w * f1.x; acc3 += w * f1.y;
    }
    float dinv = 1.f / (float)(end - beg);
    const float* bp = bias + sub * 128 + lane * 4;
    float v0 = acc0 * dinv + bp[0], v1 = acc1 * dinv + bp[1];
    float v2 = acc2 * dinv + bp[2], v3 = acc3 * dinv + bp[3];
    if (RELU) {
        v0 = fmaxf(v0, 0.f); v1 = fmaxf(v1, 0.f);
        v2 = fmaxf(v2, 0.f); v3 = fmaxf(v3, 0.f);
    }
    __half2 h0 = __floats2half2_rn(v0, v1), h1 = __floats2half2_rn(v2, v3);
    uint2 packed;
    packed.x = *(uint32_t*)&h0;
    packed.y = *(uint32_t*)&h1;
    *(uint2*)(ohi + (size_t)node * 256 + sub * 128 + lane * 4) = packed;
}

// ---------------- conv for last layer (H=1): one warp per node --------------------
__global__ __launch_bounds__(256) void k_conv1(const float* __restrict__ as_,
                                               const float* __restrict__ ad_,
                                               const float* __restrict__ bias,
                                               float* __restrict__ out) {
    int warp = (blockIdx.x * blockDim.x + threadIdx.x) >> 5;
    int lane = threadIdx.x & 31;
    if (warp >= NN) return;
    int beg = g_rowptr[warp], end = g_rowptr[warp + 1];

    float adh = ad_[warp];
    float mx = -1e30f, sm = 0.f;
    for (int i = beg + lane; i < end; i += 32) {
        int s = g_col[i];
        float e = as_[s] + adh;
        e = e > 0.f ? e : 0.2f * e;
        if (e > mx) { sm = sm * __expf(mx - e) + 1.f; mx = e; }
        else        { sm += __expf(e - mx); }
    }
#pragma unroll
    for (int o = 16; o; o >>= 1) {
        float mo = __shfl_xor_sync(0xffffffffu, mx, o);
        float so = __shfl_xor_sync(0xffffffffu, sm, o);
        float mn = fmaxf(mx, mo);
        sm = sm * __expf(mx - mn) + so * __expf(mo - mn);
        mx = mn;
    }
    float inv = 1.f / sm;
    float acc0 = 0.f, acc1 = 0.f;
#pragma unroll 4
    for (int i = beg; i < end; ++i) {
        int s = g_col[i];
        float e = as_[s] + adh;
        e = e > 0.f ? e : 0.2f * e;
        float w = __expf(e - mx) * inv;
        float2 f0 = __half22float2(((const __half2*)(g_hhi + (size_t)s * 64))[lane]);
        acc0 += w * f0.x; acc1 += w * f0.y;
    }
    float dinv = 1.f / (float)(end - beg);
    out[(size_t)warp * 64 + 2 * lane]     = acc0 * dinv + bias[2 * lane];
    out[(size_t)warp * 64 + 2 * lane + 1] = acc1 * dinv + bias[2 * lane + 1];
}

// ---------------- launch ----------------------------------------------------------
extern "C" void kernel_launch(void* const* d_in, const int* in_sizes, int n_in,
                              void* d_out, int out_size) {
    const float* x   = (const float*)d_in[0];
    const int*   ei  = (const int*)d_in[1];
    const float* W0  = (const float*)d_in[2];
    const float* a0s = (const float*)d_in[3];
    const float* a0d = (const float*)d_in[4];
    const float* b0  = (const float*)d_in[5];
    const float* W1  = (const float*)d_in[6];
    const float* a1s = (const float*)d_in[7];
    const float* a1d = (const float*)d_in[8];
    const float* b1  = (const float*)d_in[9];
    const float* W2  = (const float*)d_in[10];
    const float* a2s = (const float*)d_in[11];
    const float* a2d = (const float*)d_in[12];
    const float* b2  = (const float*)d_in[13];
    float* out = (float*)d_out;

    void* p;
    cudaGetSymbolAddress(&p, g_ahi);  __half* ahi = (__half*)p;
    cudaGetSymbolAddress(&p, g_hhi);  __half* hhi = (__half*)p;
    cudaGetSymbolAddress(&p, g_w0hi); __half* w0hi = (__half*)p;
    cudaGetSymbolAddress(&p, g_w0lo); __half* w0lo = (__half*)p;
    cudaGetSymbolAddress(&p, g_w1hi); __half* w1hi = (__half*)p;
    cudaGetSymbolAddress(&p, g_w1lo); __half* w1lo = (__half*)p;
    cudaGetSymbolAddress(&p, g_w2hi); __half* w2hi = (__half*)p;
    cudaGetSymbolAddress(&p, g_w2lo); __half* w2lo = (__half*)p;
    cudaGetSymbolAddress(&p, g_as);   float* asb = (float*)p;
    cudaGetSymbolAddress(&p, g_ad);   float* adb = (float*)p;

    const int SMEM256 = 2 * (128 * 128 + 2 * 128 * 128);  // 98304
    const int SMEM64  = 2 * (128 * 128 + 2 * 64 * 128);   // 65536

    static cudaStream_t s2 = nullptr;
    static cudaEvent_t ev_fork, ev_w0, ev_join;
    if (!s2) {
        cudaFuncSetAttribute(k_gemm_mma<256>, cudaFuncAttributeMaxDynamicSharedMemorySize, SMEM256);
        cudaFuncSetAttribute(k_gemm_mma<64>,  cudaFuncAttributeMaxDynamicSharedMemorySize, SMEM64);
        cudaStreamCreateWithFlags(&s2, cudaStreamNonBlocking);
        cudaEventCreateWithFlags(&ev_fork, cudaEventDisableTiming);
        cudaEventCreateWithFlags(&ev_w0,   cudaEventDisableTiming);
        cudaEventCreateWithFlags(&ev_join, cudaEventDisableTiming);
    }

    const int CONV4_BLKS = (2 * NN + 7) / 8;   // 2 warps per node, 8 warps per block
    const int CONV1_BLKS = (NN + 7) / 8;
    dim3 g256(2, (NN + 127) / 128);
    dim3 g64(1, (NN + 127) / 128);

    // fork: side stream does W0 split first, then CSR build + W1/W2 splits
    cudaEventRecord(ev_fork, 0);
    cudaStreamWaitEvent(s2, ev_fork, 0);
    k_split_wt<256><<<(256 * 256 + 255) / 256, 256, 0, s2>>>(W0, w0hi, w0lo);
    cudaEventRecord(ev_w0, s2);
    k_zero_cnt<<<(NN + 255) / 256, 256, 0, s2>>>();
    k_count<<<(ET + 255) / 256, 256, 0, s2>>>(ei);
    k_scan1<<<NBLK, SCAN_B, 0, s2>>>();
    k_scan2<<<1, 32, 0, s2>>>();
    k_scan3<<<(NN + 255) / 256, 256, 0, s2>>>();
    k_fill<<<(ET + 255) / 256, 256, 0, s2>>>(ei);
    k_split_wt<256><<<(256 * 256 + 255) / 256, 256, 0, s2>>>(W1, w1hi, w1lo);
    k_split_wt<64><<<(256 * 64 + 255) / 256, 256, 0, s2>>>(W2, w2hi, w2lo);
    cudaEventRecord(ev_join, s2);

    // main stream: layer-0 GEMM chain
    k_tofp16_x<<<(NN * 64 + 255) / 256, 256>>>(x);
    cudaStreamWaitEvent(0, ev_w0, 0);
    k_gemm_mma<256><<<g256, 256, SMEM256>>>(ahi, w0hi, w0lo, hhi, a0s, a0d);

    // join: conv0 needs CSR (+ W1/W2 ready for later)
    cudaStreamWaitEvent(0, ev_join, 0);
    k_conv4<true><<<CONV4_BLKS, 256>>>(asb, adb, b0, ahi);

    // layer 1
    k_gemm_mma<256><<<g256, 256, SMEM256>>>(ahi, w1hi, w1lo, hhi, a1s, a1d);
    k_conv4<true><<<CONV4_BLKS, 256>>>(asb, adb, b1, ahi);

    // layer 2 (heads=1, alpha fused in GEMM epilogue)
    k_gemm_mma<64><<<g64, 256, SMEM64>>>(ahi, w2hi, w2lo, hhi, a2s, a2d);
    k_conv1<<<CONV1_BLKS, 256>>>(asb, adb, b2, out);
}

// round 13
// speedup vs baseline: 1.2535x; 1.2535x over previous
#include <cuda_runtime.h>
#include <cuda_fp16.h>
#include <cstdint>

#define NN 50000
#define EE 600000
#define ET (EE + NN)
#define SCAN_B 1024
#define NBLK ((NN + SCAN_B - 1) / SCAN_B)

// ---------------- scratch ---------------------------------------------------------
__device__ __half g_ahi[(size_t)NN * 256];      // layer input (fp16)
__device__ __half g_hhi[(size_t)NN * 256];      // GEMM output hi
__device__ __half g_w0hi[256 * 256], g_w0lo[256 * 256];
__device__ __half g_w1hi[256 * 256], g_w1lo[256 * 256];
__device__ __half g_w2hi[64 * 256],  g_w2lo[64 * 256];
__device__ float g_as[NN * 4];
__device__ float g_ad[NN * 4];
__device__ float g_ew[(size_t)ET * 4];          // per-edge exp weights (4 heads)
__device__ int   g_cnt[NN];
__device__ int   g_incl[NBLK * SCAN_B];
__device__ int   g_bsum[NBLK];
__device__ int   g_rowptr[NN + 1];
__device__ int   g_fill[NN];
__device__ int   g_col[ET];

// ---------------- PTX helpers -----------------------------------------------------
__device__ __forceinline__ uint32_t smem_u32(const void* p) {
    uint32_t a;
    asm("{ .reg .u64 t; cvta.to.shared.u64 t, %1; cvt.u32.u64 %0, t; }" : "=r"(a) : "l"(p));
    return a;
}
__device__ __forceinline__ void cp_async16(uint32_t dst, const void* src) {
    asm volatile("cp.async.cg.shared.global [%0], [%1], 16;"
                 :: "r"(dst), "l"(__cvta_generic_to_global(src)) : "memory");
}
__device__ __forceinline__ void ldsm_x4(uint32_t& r0, uint32_t& r1, uint32_t& r2,
                                        uint32_t& r3, uint32_t addr) {
    asm volatile("ldmatrix.sync.aligned.m8n8.x4.shared.b16 {%0,%1,%2,%3}, [%4];"
                 : "=r"(r0), "=r"(r1), "=r"(r2), "=r"(r3) : "r"(addr));
}
__device__ __forceinline__ void mma16816(float* c, const uint32_t* a, const uint32_t* b) {
    asm volatile("mma.sync.aligned.m16n8k16.row.col.f32.f16.f16.f32 "
                 "{%0,%1,%2,%3}, {%4,%5,%6,%7}, {%8,%9}, {%0,%1,%2,%3};"
                 : "+f"(c[0]), "+f"(c[1]), "+f"(c[2]), "+f"(c[3])
                 : "r"(a[0]), "r"(a[1]), "r"(a[2]), "r"(a[3]), "r"(b[0]), "r"(b[1]));
}
#define SW128(o) ((o) ^ (((o) >> 3) & 0x70))

__device__ __forceinline__ void split2(float v, __half& hi, __half& lo) {
    hi = __float2half_rn(v);
    lo = __float2half_rn(v - __half2float(hi));
}

// ---------------- conversions -----------------------------------------------------
__global__ void k_tofp16_x(const float* __restrict__ x) {
    int i = blockIdx.x * blockDim.x + threadIdx.x;
    if (i >= NN * 64) return;
    float4 v = ((const float4*)x)[i];
    ((__half2*)g_ahi)[2 * i]     = __floats2half2_rn(v.x, v.y);
    ((__half2*)g_ahi)[2 * i + 1] = __floats2half2_rn(v.z, v.w);
}

template <int NO>
__global__ void k_split_wt(const float* __restrict__ W, __half* __restrict__ hi,
                           __half* __restrict__ lo) {
    int i = blockIdx.x * blockDim.x + threadIdx.x;
    if (i >= 256 * NO) return;
    int k = i / NO, n = i % NO;
    __half h, l;
    split2(W[i], h, l);
    hi[n * 256 + k] = h;
    lo[n * 256 + k] = l;
}

// ---------------- GEMM: 8 warps, A fp16, B hi/lo (2 passes), fused alpha ----------
template <int NO>
__global__ __launch_bounds__(256, 2) void k_gemm_mma(const __half* __restrict__ A,
                                                     const __half* __restrict__ Bhi,
                                                     const __half* __restrict__ Blo,
                                                     __half* __restrict__ Hhi,
                                                     const float* __restrict__ a_s,
                                                     const float* __restrict__ a_d) {
    constexpr int BM = 128, BN = (NO == 256) ? 128 : 64;
    constexpr int WN = BN / 2;
    constexpr int NG = WN / 8;
    constexpr int ASZ = 128 * 128;
    constexpr int BSZ = BN * 128;
    constexpr int STG = ASZ + 2 * BSZ;

    extern __shared__ __align__(1024) char smraw[];
    const uint32_t sb = smem_u32(smraw);
    const int tid = threadIdx.x, w = tid >> 5, lane = tid & 31;
    const int wm = w & 3, wn = w >> 2;
    const int bm = blockIdx.y * BM, bn = blockIdx.x * BN;

    auto load = [&](int c) {
        const uint32_t st = sb + (c & 1) * STG;
        const int ko = c * 64;
        for (int t = tid; t < 128 * 8; t += 256) {
            int r = t >> 3, q = t & 7;
            int gr = bm + r; if (gr >= NN) gr = NN - 1;
            cp_async16(st + SW128(r * 128 + q * 16), A + (size_t)gr * 256 + ko + q * 8);
        }
        for (int t = tid; t < BN * 8; t += 256) {
            int r = t >> 3, q = t & 7;
            size_t go = (size_t)(bn + r) * 256 + ko + q * 8;
            uint32_t so = SW128(r * 128 + q * 16);
            cp_async16(st + ASZ + so, Bhi + go);
            cp_async16(st + ASZ + BSZ + so, Blo + go);
        }
        asm volatile("cp.async.commit_group;" ::: "memory");
    };

    load(0);
    load(1);

    float acc[2][NG][4] = {};
    const int a_row = wm * 32 + (lane & 15);
    const int a_colq = (lane >> 4) * 16;
    const int b_row = wn * WN + (lane >> 4) * 8 + (lane & 7);
    const int b_colq = ((lane >> 3) & 1) * 16;

    for (int c = 0; c < 4; ++c) {
        const uint32_t st = sb + (c & 1) * STG;
        if (c < 3) asm volatile("cp.async.wait_group 1;" ::: "memory");
        else       asm volatile("cp.async.wait_group 0;" ::: "memory");
        __syncthreads();
#pragma unroll
        for (int kk = 0; kk < 4; ++kk) {
            uint32_t ah[8], bb[2 * NG];
#pragma unroll
            for (int f = 0; f < 2; ++f)
                ldsm_x4(ah[f * 4], ah[f * 4 + 1], ah[f * 4 + 2], ah[f * 4 + 3],
                        st + SW128((a_row + f * 16) * 128 + kk * 32 + a_colq));
#pragma unroll
            for (int g2 = 0; g2 < NG / 2; ++g2)
                ldsm_x4(bb[g2 * 4], bb[g2 * 4 + 1], bb[g2 * 4 + 2], bb[g2 * 4 + 3],
                        st + ASZ + SW128((b_row + g2 * 16) * 128 + kk * 32 + b_colq));
#pragma unroll
            for (int f = 0; f < 2; ++f)
#pragma unroll
                for (int g = 0; g < NG; ++g)
                    mma16816(acc[f][g], ah + f * 4, bb + g * 2);
#pragma unroll
            for (int g2 = 0; g2 < NG / 2; ++g2)
                ldsm_x4(bb[g2 * 4], bb[g2 * 4 + 1], bb[g2 * 4 + 2], bb[g2 * 4 + 3],
                        st + ASZ + BSZ + SW128((b_row + g2 * 16) * 128 + kk * 32 + b_colq));
#pragma unroll
            for (int f = 0; f < 2; ++f)
#pragma unroll
                for (int g = 0; g < NG; ++g)
                    mma16816(acc[f][g], ah + f * 4, bb + g * 2);
        }
        __syncthreads();
        if (c + 2 < 4) load(c + 2);
    }

    if constexpr (NO == 256) {
        const int head = blockIdx.x * 2 + wn;
        float as_r[2 * NG], ad_r[2 * NG];
#pragma unroll
        for (int g = 0; g < NG; ++g) {
            int cl = head * 64 + g * 8 + (lane & 3) * 2;
            as_r[g * 2] = a_s[cl];     as_r[g * 2 + 1] = a_s[cl + 1];
            ad_r[g * 2] = a_d[cl];     ad_r[g * 2 + 1] = a_d[cl + 1];
        }
#pragma unroll
        for (int f = 0; f < 2; ++f) {
#pragma unroll
            for (int rr = 0; rr < 2; ++rr) {
                float ps = 0.f, pd = 0.f;
#pragma unroll
                for (int g = 0; g < NG; ++g) {
                    float c0 = acc[f][g][rr * 2], c1 = acc[f][g][rr * 2 + 1];
                    ps += c0 * as_r[g * 2] + c1 * as_r[g * 2 + 1];
                    pd += c0 * ad_r[g * 2] + c1 * ad_r[g * 2 + 1];
                }
                ps += __shfl_xor_sync(0xffffffffu, ps, 1);
                ps += __shfl_xor_sync(0xffffffffu, ps, 2);
                pd += __shfl_xor_sync(0xffffffffu, pd, 1);
                pd += __shfl_xor_sync(0xffffffffu, pd, 2);
                int m = bm + wm * 32 + f * 16 + rr * 8 + (lane >> 2);
                if ((lane & 3) == 0 && m < NN) {
                    g_as[m * 4 + head] = ps;
                    g_ad[m * 4 + head] = pd;
                }
            }
        }
#pragma unroll
        for (int f = 0; f < 2; ++f) {
#pragma unroll
            for (int g = 0; g < NG; ++g) {
                int m = bm + wm * 32 + f * 16 + (lane >> 2);
                int n = bn + wn * 64 + g * 8 + (lane & 3) * 2;
#pragma unroll
                for (int rr = 0; rr < 2; ++rr) {
                    int mm = m + rr * 8;
                    if (mm < NN)
                        *(__half2*)(Hhi + (size_t)mm * NO + n) =
                            __floats2half2_rn(acc[f][g][rr * 2], acc[f][g][rr * 2 + 1]);
                }
            }
        }
    } else {
        // store Hhi
#pragma unroll
        for (int f = 0; f < 2; ++f) {
#pragma unroll
            for (int g = 0; g < NG; ++g) {
                int m = bm + wm * 32 + f * 16 + (lane >> 2);
                int n = bn + wn * WN + g * 8 + (lane & 3) * 2;
#pragma unroll
                for (int rr = 0; rr < 2; ++rr) {
                    int mm = m + rr * 8;
                    if (mm < NN)
                        *(__half2*)(Hhi + (size_t)mm * NO + n) =
                            __floats2half2_rn(acc[f][g][rr * 2], acc[f][g][rr * 2 + 1]);
                }
            }
        }
        // fused alpha (H=1): cross-warp (wn 0/1) reduction via reused tile smem
        float as_r[2 * NG], ad_r[2 * NG];
#pragma unroll
        for (int g = 0; g < NG; ++g) {
            int cl = wn * 32 + g * 8 + (lane & 3) * 2;
            as_r[g * 2] = a_s[cl];     as_r[g * 2 + 1] = a_s[cl + 1];
            ad_r[g * 2] = a_d[cl];     ad_r[g * 2 + 1] = a_d[cl + 1];
        }
        float psv[2][2], pdv[2][2];
#pragma unroll
        for (int f = 0; f < 2; ++f) {
#pragma unroll
            for (int rr = 0; rr < 2; ++rr) {
                float ps = 0.f, pd = 0.f;
#pragma unroll
                for (int g = 0; g < NG; ++g) {
                    float c0 = acc[f][g][rr * 2], c1 = acc[f][g][rr * 2 + 1];
                    ps += c0 * as_r[g * 2] + c1 * as_r[g * 2 + 1];
                    pd += c0 * ad_r[g * 2] + c1 * ad_r[g * 2 + 1];
                }
                ps += __shfl_xor_sync(0xffffffffu, ps, 1);
                ps += __shfl_xor_sync(0xffffffffu, ps, 2);
                pd += __shfl_xor_sync(0xffffffffu, pd, 1);
                pd += __shfl_xor_sync(0xffffffffu, pd, 2);
                psv[f][rr] = ps; pdv[f][rr] = pd;
            }
        }
        float* red = (float*)smraw;
        if (wn == 0 && (lane & 3) == 0) {
#pragma unroll
            for (int f = 0; f < 2; ++f)
#pragma unroll
                for (int rr = 0; rr < 2; ++rr) {
                    int row = wm * 32 + f * 16 + rr * 8 + (lane >> 2);
                    red[row] = psv[f][rr];
                    red[128 + row] = pdv[f][rr];
                }
        }
        __syncthreads();
        if (wn == 1 && (lane & 3) == 0) {
#pragma unroll
            for (int f = 0; f < 2; ++f)
#pragma unroll
                for (int rr = 0; rr < 2; ++rr) {
                    int row = wm * 32 + f * 16 + rr * 8 + (lane >> 2);
                    int m = bm + row;
                    if (m < NN) {
                        g_as[m] = red[row] + psv[f][rr];
                        g_ad[m] = red[128 + row] + pdv[f][rr];
                    }
                }
        }
    }
}

// ---------------- CSR build -------------------------------------------------------
__global__ void k_zero_cnt() {
    int i = blockIdx.x * blockDim.x + threadIdx.x;
    if (i < NN) g_cnt[i] = 0;
}
__global__ void k_count(const int* __restrict__ ei) {
    int e = blockIdx.x * blockDim.x + threadIdx.x;
    if (e >= ET) return;
    int d = (e < EE) ? ei[EE + e] : (e - EE);
    atomicAdd(&g_cnt[d], 1);
}
__global__ void k_scan1() {
    __shared__ int sh[SCAN_B];
    int tid = threadIdx.x;
    int i = blockIdx.x * SCAN_B + tid;
    int v = (i < NN) ? g_cnt[i] : 0;
    sh[tid] = v;
    __syncthreads();
    for (int off = 1; off < SCAN_B; off <<= 1) {
        int t = (tid >= off) ? sh[tid - off] : 0;
        __syncthreads();
        sh[tid] += t;
        __syncthreads();
    }
    g_incl[i] = sh[tid];
    if (tid == SCAN_B - 1) g_bsum[blockIdx.x] = sh[tid];
}
__global__ void k_scan2() {
    if (threadIdx.x == 0) {
        int s = 0;
        for (int i = 0; i < NBLK; ++i) { int t = g_bsum[i]; g_bsum[i] = s; s += t; }
    }
}
__global__ void k_scan3() {
    int i = blockIdx.x * blockDim.x + threadIdx.x;
    if (i < NN) {
        int v = g_cnt[i];
        int ex = g_incl[i] - v + g_bsum[i >> 10];
        g_rowptr[i] = ex;
        g_fill[i] = ex;
    }
    if (i == 0) g_rowptr[NN] = ET;
}
__global__ void k_fill(const int* __restrict__ ei) {
    int e = blockIdx.x * blockDim.x + threadIdx.x;
    if (e >= ET) return;
    int s, d;
    if (e < EE) { s = ei[e]; d = ei[EE + e]; }
    else        { s = e - EE; d = s; }
    int pos = atomicAdd(&g_fill[d], 1);
    g_col[pos] = s;
}

// ---------------- conv H=4: one warp/node; no-max softmax; staged exp weights -----
template <bool RELU>
__global__ __launch_bounds__(256) void k_conv4(const float* __restrict__ as_,
                                               const float* __restrict__ ad_,
                                               const float* __restrict__ bias,
                                               __half* __restrict__ ohi) {
    int warp = (blockIdx.x * blockDim.x + threadIdx.x) >> 5;
    int lane = threadIdx.x & 31;
    if (warp >= NN) return;
    int beg = g_rowptr[warp], end = g_rowptr[warp + 1];

    float adh0 = ad_[warp * 4 + 0], adh1 = ad_[warp * 4 + 1];
    float adh2 = ad_[warp * 4 + 2], adh3 = ad_[warp * 4 + 3];

    // pass 1: sum of exp(e) (no max shift; logits are O(1)); stage exp(e) per edge
    float s0 = 0.f, s1 = 0.f, s2 = 0.f, s3 = 0.f;
    for (int i = beg + lane; i < end; i += 32) {
        int s = g_col[i];
        float4 a4 = ((const float4*)as_)[s];
        float e0 = a4.x + adh0; e0 = e0 > 0.f ? e0 : 0.2f * e0;
        float e1 = a4.y + adh1; e1 = e1 > 0.f ? e1 : 0.2f * e1;
        float e2 = a4.z + adh2; e2 = e2 > 0.f ? e2 : 0.2f * e2;
        float e3 = a4.w + adh3; e3 = e3 > 0.f ? e3 : 0.2f * e3;
        float x0 = __expf(e0), x1 = __expf(e1), x2 = __expf(e2), x3 = __expf(e3);
        s0 += x0; s1 += x1; s2 += x2; s3 += x3;
        ((float4*)g_ew)[i] = make_float4(x0, x1, x2, x3);
    }
#pragma unroll
    for (int o = 16; o; o >>= 1) {
        s0 += __shfl_xor_sync(0xffffffffu, s0, o);
        s1 += __shfl_xor_sync(0xffffffffu, s1, o);
        s2 += __shfl_xor_sync(0xffffffffu, s2, o);
        s3 += __shfl_xor_sync(0xffffffffu, s3, o);
    }
    __threadfence_block();
    __syncwarp();

    const int myhead = lane >> 3;  // lane owns 8 channels; head = lane/8
    float smh = myhead == 0 ? s0 : (myhead == 1 ? s1 : (myhead == 2 ? s2 : s3));
    float inv = 1.f / smh;
    float acc[8] = {};
#pragma unroll 4
    for (int i = beg; i < end; ++i) {
        int s = g_col[i];
        float w = g_ew[(size_t)i * 4 + myhead] * inv;
        uint4 raw = *(const uint4*)(g_hhi + (size_t)s * 256 + lane * 8);
        float2 f0 = __half22float2(*(__half2*)&raw.x);
        float2 f1 = __half22float2(*(__half2*)&raw.y);
        float2 f2 = __half22float2(*(__half2*)&raw.z);
        float2 f3 = __half22float2(*(__half2*)&raw.w);
        acc[0] += w * f0.x; acc[1] += w * f0.y; acc[2] += w * f1.x; acc[3] += w * f1.y;
        acc[4] += w * f2.x; acc[5] += w * f2.y; acc[6] += w * f3.x; acc[7] += w * f3.y;
    }
    float dinv = 1.f / (float)(end - beg);
    float v[8];
#pragma unroll
    for (int j = 0; j < 8; ++j) {
        v[j] = acc[j] * dinv + bias[lane * 8 + j];
        if (RELU) v[j] = fmaxf(v[j], 0.f);
    }
    __half2 vh[4];
#pragma unroll
    for (int j = 0; j < 4; ++j)
        vh[j] = __floats2half2_rn(v[2 * j], v[2 * j + 1]);
    *(uint4*)(ohi + (size_t)warp * 256 + lane * 8) = *(uint4*)vh;
}

// ---------------- conv H=1 (last layer) -------------------------------------------
__global__ __launch_bounds__(256) void k_conv1(const float* __restrict__ as_,
                                               const float* __restrict__ ad_,
                                               const float* __restrict__ bias,
                                               float* __restrict__ out) {
    int warp = (blockIdx.x * blockDim.x + threadIdx.x) >> 5;
    int lane = threadIdx.x & 31;
    if (warp >= NN) return;
    int beg = g_rowptr[warp], end = g_rowptr[warp + 1];

    float adh = ad_[warp];
    float sm = 0.f;
    for (int i = beg + lane; i < end; i += 32) {
        int s = g_col[i];
        float e = as_[s] + adh;
        e = e > 0.f ? e : 0.2f * e;
        float x = __expf(e);
        sm += x;
        g_ew[i] = x;
    }
#pragma unroll
    for (int o = 16; o; o >>= 1)
        sm += __shfl_xor_sync(0xffffffffu, sm, o);
    __threadfence_block();
    __syncwarp();

    float inv = 1.f / sm;
    float acc0 = 0.f, acc1 = 0.f;
#pragma unroll 4
    for (int i = beg; i < end; ++i) {
        int s = g_col[i];
        float w = g_ew[i] * inv;
        float2 f0 = __half22float2(((const __half2*)(g_hhi + (size_t)s * 64))[lane]);
        acc0 += w * f0.x; acc1 += w * f0.y;
    }
    float dinv = 1.f / (float)(end - beg);
    out[(size_t)warp * 64 + 2 * lane]     = acc0 * dinv + bias[2 * lane];
    out[(size_t)warp * 64 + 2 * lane + 1] = acc1 * dinv + bias[2 * lane + 1];
}

// ---------------- launch ----------------------------------------------------------
extern "C" void kernel_launch(void* const* d_in, const int* in_sizes, int n_in,
                              void* d_out, int out_size) {
    const float* x   = (const float*)d_in[0];
    const int*   ei  = (const int*)d_in[1];
    const float* W0  = (const float*)d_in[2];
    const float* a0s = (const float*)d_in[3];
    const float* a0d = (const float*)d_in[4];
    const float* b0  = (const float*)d_in[5];
    const float* W1  = (const float*)d_in[6];
    const float* a1s = (const float*)d_in[7];
    const float* a1d = (const float*)d_in[8];
    const float* b1  = (const float*)d_in[9];
    const float* W2  = (const float*)d_in[10];
    const float* a2s = (const float*)d_in[11];
    const float* a2d = (const float*)d_in[12];
    const float* b2  = (const float*)d_in[13];
    float* out = (float*)d_out;

    void* p;
    cudaGetSymbolAddress(&p, g_ahi);  __half* ahi = (__half*)p;
    cudaGetSymbolAddress(&p, g_hhi);  __half* hhi = (__half*)p;
    cudaGetSymbolAddress(&p, g_w0hi); __half* w0hi = (__half*)p;
    cudaGetSymbolAddress(&p, g_w0lo); __half* w0lo = (__half*)p;
    cudaGetSymbolAddress(&p, g_w1hi); __half* w1hi = (__half*)p;
    cudaGetSymbolAddress(&p, g_w1lo); __half* w1lo = (__half*)p;
    cudaGetSymbolAddress(&p, g_w2hi); __half* w2hi = (__half*)p;
    cudaGetSymbolAddress(&p, g_w2lo); __half* w2lo = (__half*)p;
    cudaGetSymbolAddress(&p, g_as);   float* asb = (float*)p;
    cudaGetSymbolAddress(&p, g_ad);   float* adb = (float*)p;

    const int SMEM256 = 2 * (128 * 128 + 2 * 128 * 128);  // 98304
    const int SMEM64  = 2 * (128 * 128 + 2 * 64 * 128);   // 65536

    static cudaStream_t s2 = nullptr;
    static cudaEvent_t ev_fork, ev_w0, ev_join;
    if (!s2) {
        cudaFuncSetAttribute(k_gemm_mma<256>, cudaFuncAttributeMaxDynamicSharedMemorySize, SMEM256);
        cudaFuncSetAttribute(k_gemm_mma<64>,  cudaFuncAttributeMaxDynamicSharedMemorySize, SMEM64);
        cudaStreamCreateWithFlags(&s2, cudaStreamNonBlocking);
        cudaEventCreateWithFlags(&ev_fork, cudaEventDisableTiming);
        cudaEventCreateWithFlags(&ev_w0,   cudaEventDisableTiming);
        cudaEventCreateWithFlags(&ev_join, cudaEventDisableTiming);
    }

    const int NODE_BLKS = (NN + 7) / 8;
    dim3 g256(2, (NN + 127) / 128);
    dim3 g64(1, (NN + 127) / 128);

    // fork: side stream does W0 split first, then CSR build + W1/W2 splits
    cudaEventRecord(ev_fork, 0);
    cudaStreamWaitEvent(s2, ev_fork, 0);
    k_split_wt<256><<<(256 * 256 + 255) / 256, 256, 0, s2>>>(W0, w0hi, w0lo);
    cudaEventRecord(ev_w0, s2);
    k_zero_cnt<<<(NN + 255) / 256, 256, 0, s2>>>();
    k_count<<<(ET + 255) / 256, 256, 0, s2>>>(ei);
    k_scan1<<<NBLK, SCAN_B, 0, s2>>>();
    k_scan2<<<1, 32, 0, s2>>>();
    k_scan3<<<(NN + 255) / 256, 256, 0, s2>>>();
    k_fill<<<(ET + 255) / 256, 256, 0, s2>>>(ei);
    k_split_wt<256><<<(256 * 256 + 255) / 256, 256, 0, s2>>>(W1, w1hi, w1lo);
    k_split_wt<64><<<(256 * 64 + 255) / 256, 256, 0, s2>>>(W2, w2hi, w2lo);
    cudaEventRecord(ev_join, s2);

    // main stream: layer-0 GEMM chain
    k_tofp16_x<<<(NN * 64 + 255) / 256, 256>>>(x);
    cudaStreamWaitEvent(0, ev_w0, 0);
    k_gemm_mma<256><<<g256, 256, SMEM256>>>(ahi, w0hi, w0lo, hhi, a0s, a0d);

    // join: conv0 needs CSR (+ W1/W2 ready for later)
    cudaStreamWaitEvent(0, ev_join, 0);
    k_conv4<true><<<NODE_BLKS, 256>>>(asb, adb, b0, ahi);

    // layer 1
    k_gemm_mma<256><<<g256, 256, SMEM256>>>(ahi, w1hi, w1lo, hhi, a1s, a1d);
    k_conv4<true><<<NODE_BLKS, 256>>>(asb, adb, b1, ahi);

    // layer 2 (heads=1, alpha fused in GEMM epilogue)
    k_gemm_mma<64><<<g64, 256, SMEM64>>>(ahi, w2hi, w2lo, hhi, a2s, a2d);
    k_conv1<<<NODE_BLKS, 256>>>(asb, adb, b2, out);
}

// round 14
// speedup vs baseline: 1.3186x; 1.0519x over previous
#include <cuda_runtime.h>
#include <cuda_fp16.h>
#include <cstdint>

#define NN 50000
#define EE 600000
#define ET (EE + NN)
#define SCAN_B 1024
#define NBLK ((NN + SCAN_B - 1) / SCAN_B)

// ---------------- scratch ---------------------------------------------------------
__device__ __half g_ahi[(size_t)NN * 256];      // layer input (fp16)
__device__ __half g_hhi[(size_t)NN * 256];      // GEMM output hi
__device__ __half g_w0hi[256 * 256];
__device__ __half g_w1hi[256 * 256], g_w1lo[256 * 256];
__device__ __half g_w2hi[64 * 256],  g_w2lo[64 * 256];
__device__ float g_as[NN * 4];
__device__ float g_ad[NN * 4];
__device__ float g_ew[(size_t)ET * 4];          // per-edge exp weights (4 heads)
__device__ int   g_cnt[NN];
__device__ int   g_incl[NBLK * SCAN_B];
__device__ int   g_bsum[NBLK];
__device__ int   g_rowptr[NN + 1];
__device__ int   g_fill[NN];
__device__ int   g_col[ET];

// ---------------- PTX helpers -----------------------------------------------------
__device__ __forceinline__ uint32_t smem_u32(const void* p) {
    uint32_t a;
    asm("{ .reg .u64 t; cvta.to.shared.u64 t, %1; cvt.u32.u64 %0, t; }" : "=r"(a) : "l"(p));
    return a;
}
__device__ __forceinline__ void cp_async16(uint32_t dst, const void* src) {
    asm volatile("cp.async.cg.shared.global [%0], [%1], 16;"
                 :: "r"(dst), "l"(__cvta_generic_to_global(src)) : "memory");
}
__device__ __forceinline__ void ldsm_x4(uint32_t& r0, uint32_t& r1, uint32_t& r2,
                                        uint32_t& r3, uint32_t addr) {
    asm volatile("ldmatrix.sync.aligned.m8n8.x4.shared.b16 {%0,%1,%2,%3}, [%4];"
                 : "=r"(r0), "=r"(r1), "=r"(r2), "=r"(r3) : "r"(addr));
}
__device__ __forceinline__ void mma16816(float* c, const uint32_t* a, const uint32_t* b) {
    asm volatile("mma.sync.aligned.m16n8k16.row.col.f32.f16.f16.f32 "
                 "{%0,%1,%2,%3}, {%4,%5,%6,%7}, {%8,%9}, {%0,%1,%2,%3};"
                 : "+f"(c[0]), "+f"(c[1]), "+f"(c[2]), "+f"(c[3])
                 : "r"(a[0]), "r"(a[1]), "r"(a[2]), "r"(a[3]), "r"(b[0]), "r"(b[1]));
}
#define SW128(o) ((o) ^ (((o) >> 3) & 0x70))

__device__ __forceinline__ void split2(float v, __half& hi, __half& lo) {
    hi = __float2half_rn(v);
    lo = __float2half_rn(v - __half2float(hi));
}

// ---------------- conversions -----------------------------------------------------
__global__ void k_tofp16_x(const float* __restrict__ x) {
    int i = blockIdx.x * blockDim.x + threadIdx.x;
    if (i >= NN * 64) return;
    float4 v = ((const float4*)x)[i];
    ((__half2*)g_ahi)[2 * i]     = __floats2half2_rn(v.x, v.y);
    ((__half2*)g_ahi)[2 * i + 1] = __floats2half2_rn(v.z, v.w);
}

// hi-only weight transpose+convert (layer 0)
__global__ void k_wt_hi(const float* __restrict__ W, __half* __restrict__ hi) {
    int i = blockIdx.x * blockDim.x + threadIdx.x;
    if (i >= 256 * 256) return;
    int k = i / 256, n = i % 256;
    hi[n * 256 + k] = __float2half_rn(W[i]);
}

template <int NO>
__global__ void k_split_wt(const float* __restrict__ W, __half* __restrict__ hi,
                           __half* __restrict__ lo) {
    int i = blockIdx.x * blockDim.x + threadIdx.x;
    if (i >= 256 * NO) return;
    int k = i / NO, n = i % NO;
    __half h, l;
    split2(W[i], h, l);
    hi[n * 256 + k] = h;
    lo[n * 256 + k] = l;
}

// ---------------- GEMM: 8 warps, A fp16, B hi (+ optional lo pass), fused alpha ---
template <int NO, bool BLO>
__global__ __launch_bounds__(256, 2) void k_gemm_mma(const __half* __restrict__ A,
                                                     const __half* __restrict__ Bhi,
                                                     const __half* __restrict__ Blo,
                                                     __half* __restrict__ Hhi,
                                                     const float* __restrict__ a_s,
                                                     const float* __restrict__ a_d) {
    constexpr int BM = 128, BN = (NO == 256) ? 128 : 64;
    constexpr int WN = BN / 2;
    constexpr int NG = WN / 8;
    constexpr int ASZ = 128 * 128;
    constexpr int BSZ = BN * 128;
    constexpr int NB = BLO ? 2 : 1;
    constexpr int STG = ASZ + NB * BSZ;

    extern __shared__ __align__(1024) char smraw[];
    const uint32_t sb = smem_u32(smraw);
    const int tid = threadIdx.x, w = tid >> 5, lane = tid & 31;
    const int wm = w & 3, wn = w >> 2;
    const int bm = blockIdx.y * BM, bn = blockIdx.x * BN;

    auto load = [&](int c) {
        const uint32_t st = sb + (c & 1) * STG;
        const int ko = c * 64;
        for (int t = tid; t < 128 * 8; t += 256) {
            int r = t >> 3, q = t & 7;
            int gr = bm + r; if (gr >= NN) gr = NN - 1;
            cp_async16(st + SW128(r * 128 + q * 16), A + (size_t)gr * 256 + ko + q * 8);
        }
        for (int t = tid; t < BN * 8; t += 256) {
            int r = t >> 3, q = t & 7;
            size_t go = (size_t)(bn + r) * 256 + ko + q * 8;
            uint32_t so = SW128(r * 128 + q * 16);
            cp_async16(st + ASZ + so, Bhi + go);
            if (BLO) cp_async16(st + ASZ + BSZ + so, Blo + go);
        }
        asm volatile("cp.async.commit_group;" ::: "memory");
    };

    load(0);
    load(1);

    float acc[2][NG][4] = {};
    const int a_row = wm * 32 + (lane & 15);
    const int a_colq = (lane >> 4) * 16;
    const int b_row = wn * WN + (lane >> 4) * 8 + (lane & 7);
    const int b_colq = ((lane >> 3) & 1) * 16;

    for (int c = 0; c < 4; ++c) {
        const uint32_t st = sb + (c & 1) * STG;
        if (c < 3) asm volatile("cp.async.wait_group 1;" ::: "memory");
        else       asm volatile("cp.async.wait_group 0;" ::: "memory");
        __syncthreads();
#pragma unroll
        for (int kk = 0; kk < 4; ++kk) {
            uint32_t ah[8], bb[2 * NG];
#pragma unroll
            for (int f = 0; f < 2; ++f)
                ldsm_x4(ah[f * 4], ah[f * 4 + 1], ah[f * 4 + 2], ah[f * 4 + 3],
                        st + SW128((a_row + f * 16) * 128 + kk * 32 + a_colq));
#pragma unroll
            for (int g2 = 0; g2 < NG / 2; ++g2)
                ldsm_x4(bb[g2 * 4], bb[g2 * 4 + 1], bb[g2 * 4 + 2], bb[g2 * 4 + 3],
                        st + ASZ + SW128((b_row + g2 * 16) * 128 + kk * 32 + b_colq));
#pragma unroll
            for (int f = 0; f < 2; ++f)
#pragma unroll
                for (int g = 0; g < NG; ++g)
                    mma16816(acc[f][g], ah + f * 4, bb + g * 2);
            if constexpr (BLO) {
#pragma unroll
                for (int g2 = 0; g2 < NG / 2; ++g2)
                    ldsm_x4(bb[g2 * 4], bb[g2 * 4 + 1], bb[g2 * 4 + 2], bb[g2 * 4 + 3],
                            st + ASZ + BSZ + SW128((b_row + g2 * 16) * 128 + kk * 32 + b_colq));
#pragma unroll
                for (int f = 0; f < 2; ++f)
#pragma unroll
                    for (int g = 0; g < NG; ++g)
                        mma16816(acc[f][g], ah + f * 4, bb + g * 2);
            }
        }
        __syncthreads();
        if (c + 2 < 4) load(c + 2);
    }

    if constexpr (NO == 256) {
        const int head = blockIdx.x * 2 + wn;
        float as_r[2 * NG], ad_r[2 * NG];
#pragma unroll
        for (int g = 0; g < NG; ++g) {
            int cl = head * 64 + g * 8 + (lane & 3) * 2;
            as_r[g * 2] = a_s[cl];     as_r[g * 2 + 1] = a_s[cl + 1];
            ad_r[g * 2] = a_d[cl];     ad_r[g * 2 + 1] = a_d[cl + 1];
        }
#pragma unroll
        for (int f = 0; f < 2; ++f) {
#pragma unroll
            for (int rr = 0; rr < 2; ++rr) {
                float ps = 0.f, pd = 0.f;
#pragma unroll
                for (int g = 0; g < NG; ++g) {
                    float c0 = acc[f][g][rr * 2], c1 = acc[f][g][rr * 2 + 1];
                    ps += c0 * as_r[g * 2] + c1 * as_r[g * 2 + 1];
                    pd += c0 * ad_r[g * 2] + c1 * ad_r[g * 2 + 1];
                }
                ps += __shfl_xor_sync(0xffffffffu, ps, 1);
                ps += __shfl_xor_sync(0xffffffffu, ps, 2);
                pd += __shfl_xor_sync(0xffffffffu, pd, 1);
                pd += __shfl_xor_sync(0xffffffffu, pd, 2);
                int m = bm + wm * 32 + f * 16 + rr * 8 + (lane >> 2);
                if ((lane & 3) == 0 && m < NN) {
                    g_as[m * 4 + head] = ps;
                    g_ad[m * 4 + head] = pd;
                }
            }
        }
#pragma unroll
        for (int f = 0; f < 2; ++f) {
#pragma unroll
            for (int g = 0; g < NG; ++g) {
                int m = bm + wm * 32 + f * 16 + (lane >> 2);
                int n = bn + wn * 64 + g * 8 + (lane & 3) * 2;
#pragma unroll
                for (int rr = 0; rr < 2; ++rr) {
                    int mm = m + rr * 8;
                    if (mm < NN)
                        *(__half2*)(Hhi + (size_t)mm * NO + n) =
                            __floats2half2_rn(acc[f][g][rr * 2], acc[f][g][rr * 2 + 1]);
                }
            }
        }
    } else {
#pragma unroll
        for (int f = 0; f < 2; ++f) {
#pragma unroll
            for (int g = 0; g < NG; ++g) {
                int m = bm + wm * 32 + f * 16 + (lane >> 2);
                int n = bn + wn * WN + g * 8 + (lane & 3) * 2;
#pragma unroll
                for (int rr = 0; rr < 2; ++rr) {
                    int mm = m + rr * 8;
                    if (mm < NN)
                        *(__half2*)(Hhi + (size_t)mm * NO + n) =
                            __floats2half2_rn(acc[f][g][rr * 2], acc[f][g][rr * 2 + 1]);
                }
            }
        }
        // fused alpha (H=1)
        float as_r[2 * NG], ad_r[2 * NG];
#pragma unroll
        for (int g = 0; g < NG; ++g) {
            int cl = wn * 32 + g * 8 + (lane & 3) * 2;
            as_r[g * 2] = a_s[cl];     as_r[g * 2 + 1] = a_s[cl + 1];
            ad_r[g * 2] = a_d[cl];     ad_r[g * 2 + 1] = a_d[cl + 1];
        }
        float psv[2][2], pdv[2][2];
#pragma unroll
        for (int f = 0; f < 2; ++f) {
#pragma unroll
            for (int rr = 0; rr < 2; ++rr) {
                float ps = 0.f, pd = 0.f;
#pragma unroll
                for (int g = 0; g < NG; ++g) {
                    float c0 = acc[f][g][rr * 2], c1 = acc[f][g][rr * 2 + 1];
                    ps += c0 * as_r[g * 2] + c1 * as_r[g * 2 + 1];
                    pd += c0 * ad_r[g * 2] + c1 * ad_r[g * 2 + 1];
                }
                ps += __shfl_xor_sync(0xffffffffu, ps, 1);
                ps += __shfl_xor_sync(0xffffffffu, ps, 2);
                pd += __shfl_xor_sync(0xffffffffu, pd, 1);
                pd += __shfl_xor_sync(0xffffffffu, pd, 2);
                psv[f][rr] = ps; pdv[f][rr] = pd;
            }
        }
        float* red = (float*)smraw;
        if (wn == 0 && (lane & 3) == 0) {
#pragma unroll
            for (int f = 0; f < 2; ++f)
#pragma unroll
                for (int rr = 0; rr < 2; ++rr) {
                    int row = wm * 32 + f * 16 + rr * 8 + (lane >> 2);
                    red[row] = psv[f][rr];
                    red[128 + row] = pdv[f][rr];
                }
        }
        __syncthreads();
        if (wn == 1 && (lane & 3) == 0) {
#pragma unroll
            for (int f = 0; f < 2; ++f)
#pragma unroll
                for (int rr = 0; rr < 2; ++rr) {
                    int row = wm * 32 + f * 16 + rr * 8 + (lane >> 2);
                    int m = bm + row;
                    if (m < NN) {
                        g_as[m] = red[row] + psv[f][rr];
                        g_ad[m] = red[128 + row] + pdv[f][rr];
                    }
                }
        }
    }
}

// ---------------- CSR build -------------------------------------------------------
__global__ void k_zero_cnt() {
    int i = blockIdx.x * blockDim.x + threadIdx.x;
    if (i < NN) g_cnt[i] = 0;
}
__global__ void k_count(const int* __restrict__ ei) {
    int e = blockIdx.x * blockDim.x + threadIdx.x;
    if (e >= ET) return;
    int d = (e < EE) ? ei[EE + e] : (e - EE);
    atomicAdd(&g_cnt[d], 1);
}
__global__ void k_scan1() {
    __shared__ int sh[SCAN_B];
    int tid = threadIdx.x;
    int i = blockIdx.x * SCAN_B + tid;
    int v = (i < NN) ? g_cnt[i] : 0;
    sh[tid] = v;
    __syncthreads();
    for (int off = 1; off < SCAN_B; off <<= 1) {
        int t = (tid >= off) ? sh[tid - off] : 0;
        __syncthreads();
        sh[tid] += t;
        __syncthreads();
    }
    g_incl[i] = sh[tid];
    if (tid == SCAN_B - 1) g_bsum[blockIdx.x] = sh[tid];
}
__global__ void k_scan2() {
    if (threadIdx.x == 0) {
        int s = 0;
        for (int i = 0; i < NBLK; ++i) { int t = g_bsum[i]; g_bsum[i] = s; s += t; }
    }
}
__global__ void k_scan3() {
    int i = blockIdx.x * blockDim.x + threadIdx.x;
    if (i < NN) {
        int v = g_cnt[i];
        int ex = g_incl[i] - v + g_bsum[i >> 10];
        g_rowptr[i] = ex;
        g_fill[i] = ex;
    }
    if (i == 0) g_rowptr[NN] = ET;
}
__global__ void k_fill(const int* __restrict__ ei) {
    int e = blockIdx.x * blockDim.x + threadIdx.x;
    if (e >= ET) return;
    int s, d;
    if (e < EE) { s = ei[e]; d = ei[EE + e]; }
    else        { s = e - EE; d = s; }
    int pos = atomicAdd(&g_fill[d], 1);
    g_col[pos] = s;
}

// ---------------- conv H=4: one warp/node; no-max softmax; staged exp weights -----
template <bool RELU>
__global__ __launch_bounds__(256) void k_conv4(const float* __restrict__ as_,
                                               const float* __restrict__ ad_,
                                               const float* __restrict__ bias,
                                               __half* __restrict__ ohi) {
    int warp = (blockIdx.x * blockDim.x + threadIdx.x) >> 5;
    int lane = threadIdx.x & 31;
    if (warp >= NN) return;
    int beg = g_rowptr[warp], end = g_rowptr[warp + 1];

    float adh0 = ad_[warp * 4 + 0], adh1 = ad_[warp * 4 + 1];
    float adh2 = ad_[warp * 4 + 2], adh3 = ad_[warp * 4 + 3];

    float s0 = 0.f, s1 = 0.f, s2 = 0.f, s3 = 0.f;
    for (int i = beg + lane; i < end; i += 32) {
        int s = g_col[i];
        float4 a4 = ((const float4*)as_)[s];
        float e0 = a4.x + adh0; e0 = e0 > 0.f ? e0 : 0.2f * e0;
        float e1 = a4.y + adh1; e1 = e1 > 0.f ? e1 : 0.2f * e1;
        float e2 = a4.z + adh2; e2 = e2 > 0.f ? e2 : 0.2f * e2;
        float e3 = a4.w + adh3; e3 = e3 > 0.f ? e3 : 0.2f * e3;
        float x0 = __expf(e0), x1 = __expf(e1), x2 = __expf(e2), x3 = __expf(e3);
        s0 += x0; s1 += x1; s2 += x2; s3 += x3;
        ((float4*)g_ew)[i] = make_float4(x0, x1, x2, x3);
    }
#pragma unroll
    for (int o = 16; o; o >>= 1) {
        s0 += __shfl_xor_sync(0xffffffffu, s0, o);
        s1 += __shfl_xor_sync(0xffffffffu, s1, o);
        s2 += __shfl_xor_sync(0xffffffffu, s2, o);
        s3 += __shfl_xor_sync(0xffffffffu, s3, o);
    }
    __threadfence_block();
    __syncwarp();

    const int myhead = lane >> 3;
    float smh = myhead == 0 ? s0 : (myhead == 1 ? s1 : (myhead == 2 ? s2 : s3));
    float acc[8] = {};
#pragma unroll 8
    for (int i = beg; i < end; ++i) {
        int s = g_col[i];
        float w = g_ew[(size_t)i * 4 + myhead];
        uint4 raw = *(const uint4*)(g_hhi + (size_t)s * 256 + lane * 8);
        float2 f0 = __half22float2(*(__half2*)&raw.x);
        float2 f1 = __half22float2(*(__half2*)&raw.y);
        float2 f2 = __half22float2(*(__half2*)&raw.z);
        float2 f3 = __half22float2(*(__half2*)&raw.w);
        acc[0] += w * f0.x; acc[1] += w * f0.y; acc[2] += w * f1.x; acc[3] += w * f1.y;
        acc[4] += w * f2.x; acc[5] += w * f2.y; acc[6] += w * f3.x; acc[7] += w * f3.y;
    }
    float scale = 1.f / (smh * (float)(end - beg));
    float v[8];
#pragma unroll
    for (int j = 0; j < 8; ++j) {
        v[j] = acc[j] * scale + bias[lane * 8 + j];
        if (RELU) v[j] = fmaxf(v[j], 0.f);
    }
    __half2 vh[4];
#pragma unroll
    for (int j = 0; j < 4; ++j)
        vh[j] = __floats2half2_rn(v[2 * j], v[2 * j + 1]);
    *(uint4*)(ohi + (size_t)warp * 256 + lane * 8) = *(uint4*)vh;
}

// ---------------- conv H=1 (last layer) -------------------------------------------
__global__ __launch_bounds__(256) void k_conv1(const float* __restrict__ as_,
                                               const float* __restrict__ ad_,
                                               const float* __restrict__ bias,
                                               float* __restrict__ out) {
    int warp = (blockIdx.x * blockDim.x + threadIdx.x) >> 5;
    int lane = threadIdx.x & 31;
    if (warp >= NN) return;
    int beg = g_rowptr[warp], end = g_rowptr[warp + 1];

    float adh = ad_[warp];
    float sm = 0.f;
    for (int i = beg + lane; i < end; i += 32) {
        int s = g_col[i];
        float e = as_[s] + adh;
        e = e > 0.f ? e : 0.2f * e;
        float x = __expf(e);
        sm += x;
        g_ew[i] = x;
    }
#pragma unroll
    for (int o = 16; o; o >>= 1)
        sm += __shfl_xor_sync(0xffffffffu, sm, o);
    __threadfence_block();
    __syncwarp();

    float acc0 = 0.f, acc1 = 0.f;
#pragma unroll 8
    for (int i = beg; i < end; ++i) {
        int s = g_col[i];
        float w = g_ew[i];
        float2 f0 = __half22float2(((const __half2*)(g_hhi + (size_t)s * 64))[lane]);
        acc0 += w * f0.x; acc1 += w * f0.y;
    }
    float scale = 1.f / (sm * (float)(end - beg));
    out[(size_t)warp * 64 + 2 * lane]     = acc0 * scale + bias[2 * lane];
    out[(size_t)warp * 64 + 2 * lane + 1] = acc1 * scale + bias[2 * lane + 1];
}

// ---------------- launch ----------------------------------------------------------
extern "C" void kernel_launch(void* const* d_in, const int* in_sizes, int n_in,
                              void* d_out, int out_size) {
    const float* x   = (const float*)d_in[0];
    const int*   ei  = (const int*)d_in[1];
    const float* W0  = (const float*)d_in[2];
    const float* a0s = (const float*)d_in[3];
    const float* a0d = (const float*)d_in[4];
    const float* b0  = (const float*)d_in[5];
    const float* W1  = (const float*)d_in[6];
    const float* a1s = (const float*)d_in[7];
    const float* a1d = (const float*)d_in[8];
    const float* b1  = (const float*)d_in[9];
    const float* W2  = (const float*)d_in[10];
    const float* a2s = (const float*)d_in[11];
    const float* a2d = (const float*)d_in[12];
    const float* b2  = (const float*)d_in[13];
    float* out = (float*)d_out;

    void* p;
    cudaGetSymbolAddress(&p, g_ahi);  __half* ahi = (__half*)p;
    cudaGetSymbolAddress(&p, g_hhi);  __half* hhi = (__half*)p;
    cudaGetSymbolAddress(&p, g_w0hi); __half* w0hi = (__half*)p;
    cudaGetSymbolAddress(&p, g_w1hi); __half* w1hi = (__half*)p;
    cudaGetSymbolAddress(&p, g_w1lo); __half* w1lo = (__half*)p;
    cudaGetSymbolAddress(&p, g_w2hi); __half* w2hi = (__half*)p;
    cudaGetSymbolAddress(&p, g_w2lo); __half* w2lo = (__half*)p;
    cudaGetSymbolAddress(&p, g_as);   float* asb = (float*)p;
    cudaGetSymbolAddress(&p, g_ad);   float* adb = (float*)p;

    const int SMEM0   = 2 * (128 * 128 + 128 * 128);       // 65536 (BLO=false)
    const int SMEM256 = 2 * (128 * 128 + 2 * 128 * 128);   // 98304
    const int SMEM64  = 2 * (128 * 128 + 2 * 64 * 128);    // 65536

    static cudaStream_t s2 = nullptr;
    static cudaEvent_t ev_fork, ev_w0, ev_join;
    if (!s2) {
        cudaFuncSetAttribute(k_gemm_mma<256, false>, cudaFuncAttributeMaxDynamicSharedMemorySize, SMEM0);
        cudaFuncSetAttribute(k_gemm_mma<256, true>,  cudaFuncAttributeMaxDynamicSharedMemorySize, SMEM256);
        cudaFuncSetAttribute(k_gemm_mma<64, true>,   cudaFuncAttributeMaxDynamicSharedMemorySize, SMEM64);
        cudaStreamCreateWithFlags(&s2, cudaStreamNonBlocking);
        cudaEventCreateWithFlags(&ev_fork, cudaEventDisableTiming);
        cudaEventCreateWithFlags(&ev_w0,   cudaEventDisableTiming);
        cudaEventCreateWithFlags(&ev_join, cudaEventDisableTiming);
    }

    const int NODE_BLKS = (NN + 7) / 8;
    dim3 g256(2, (NN + 127) / 128);
    dim3 g64(1, (NN + 127) / 128);

    // fork: side stream does W0 convert first, then CSR build + W1/W2 splits
    cudaEventRecord(ev_fork, 0);
    cudaStreamWaitEvent(s2, ev_fork, 0);
    k_wt_hi<<<(256 * 256 + 255) / 256, 256, 0, s2>>>(W0, w0hi);
    cudaEventRecord(ev_w0, s2);
    k_zero_cnt<<<(NN + 255) / 256, 256, 0, s2>>>();
    k_count<<<(ET + 255) / 256, 256, 0, s2>>>(ei);
    k_scan1<<<NBLK, SCAN_B, 0, s2>>>();
    k_scan2<<<1, 32, 0, s2>>>();
    k_scan3<<<(NN + 255) / 256, 256, 0, s2>>>();
    k_fill<<<(ET + 255) / 256, 256, 0, s2>>>(ei);
    k_split_wt<256><<<(256 * 256 + 255) / 256, 256, 0, s2>>>(W1, w1hi, w1lo);
    k_split_wt<64><<<(256 * 64 + 255) / 256, 256, 0, s2>>>(W2, w2hi, w2lo);
    cudaEventRecord(ev_join, s2);

    // main stream: layer-0 GEMM (single hi pass)
    k_tofp16_x<<<(NN * 64 + 255) / 256, 256>>>(x);
    cudaStreamWaitEvent(0, ev_w0, 0);
    k_gemm_mma<256, false><<<g256, 256, SMEM0>>>(ahi, w0hi, nullptr, hhi, a0s, a0d);

    // join: conv0 needs CSR
    cudaStreamWaitEvent(0, ev_join, 0);
    k_conv4<true><<<NODE_BLKS, 256>>>(asb, adb, b0, ahi);

    // layer 1 (hi/lo)
    k_gemm_mma<256, true><<<g256, 256, SMEM256>>>(ahi, w1hi, w1lo, hhi, a1s, a1d);
    k_conv4<true><<<NODE_BLKS, 256>>>(asb, adb, b1, ahi);

    // layer 2 (heads=1, hi/lo, alpha fused)
    k_gemm_mma<64, true><<<g64, 256, SMEM64>>>(ahi, w2hi, w2lo, hhi, a2s, a2d);
    k_conv1<<<NODE_BLKS, 256>>>(asb, adb, b2, out);
}

// round 15
// speedup vs baseline: 1.4066x; 1.0667x over previous
#include <cuda_runtime.h>
#include <cuda_fp16.h>
#include <cstdint>

#define NN 50000
#define EE 600000
#define ET (EE + NN)
#define SCAN_B 1024
#define NBLK ((NN + SCAN_B - 1) / SCAN_B)

// ---------------- scratch ---------------------------------------------------------
__device__ __half g_ahi[(size_t)NN * 256];      // layer input (fp16)
__device__ __half g_hhi[(size_t)NN * 256];      // GEMM output hi
__device__ __half g_w0hi[256 * 256];
__device__ __half g_w1hi[256 * 256];
__device__ __half g_w2hi[64 * 256];
__device__ float g_as[NN * 4];
__device__ float g_ad[NN * 4];
__device__ float g_ew[(size_t)ET * 4];          // per-edge exp weights (4 heads)
__device__ int   g_cnt[NN];
__device__ int   g_incl[NBLK * SCAN_B];
__device__ int   g_bsum[NBLK];
__device__ int   g_rowptr[NN + 1];
__device__ int   g_fill[NN];
__device__ int   g_col[ET];

// ---------------- PTX helpers -----------------------------------------------------
__device__ __forceinline__ uint32_t smem_u32(const void* p) {
    uint32_t a;
    asm("{ .reg .u64 t; cvta.to.shared.u64 t, %1; cvt.u32.u64 %0, t; }" : "=r"(a) : "l"(p));
    return a;
}
__device__ __forceinline__ void cp_async16(uint32_t dst, const void* src) {
    asm volatile("cp.async.cg.shared.global [%0], [%1], 16;"
                 :: "r"(dst), "l"(__cvta_generic_to_global(src)) : "memory");
}
__device__ __forceinline__ void ldsm_x4(uint32_t& r0, uint32_t& r1, uint32_t& r2,
                                        uint32_t& r3, uint32_t addr) {
    asm volatile("ldmatrix.sync.aligned.m8n8.x4.shared.b16 {%0,%1,%2,%3}, [%4];"
                 : "=r"(r0), "=r"(r1), "=r"(r2), "=r"(r3) : "r"(addr));
}
__device__ __forceinline__ void mma16816(float* c, const uint32_t* a, const uint32_t* b) {
    asm volatile("mma.sync.aligned.m16n8k16.row.col.f32.f16.f16.f32 "
                 "{%0,%1,%2,%3}, {%4,%5,%6,%7}, {%8,%9}, {%0,%1,%2,%3};"
                 : "+f"(c[0]), "+f"(c[1]), "+f"(c[2]), "+f"(c[3])
                 : "r"(a[0]), "r"(a[1]), "r"(a[2]), "r"(a[3]), "r"(b[0]), "r"(b[1]));
}
#define SW128(o) ((o) ^ (((o) >> 3) & 0x70))

// ---------------- conversions -----------------------------------------------------
__global__ void k_tofp16_x(const float* __restrict__ x) {
    int i = blockIdx.x * blockDim.x + threadIdx.x;
    if (i >= NN * 64) return;
    float4 v = ((const float4*)x)[i];
    ((__half2*)g_ahi)[2 * i]     = __floats2half2_rn(v.x, v.y);
    ((__half2*)g_ahi)[2 * i + 1] = __floats2half2_rn(v.z, v.w);
}

// hi-only weight transpose+convert: Wt[n][k] = fp16(W[k][n])
template <int NO>
__global__ void k_wt_hi(const float* __restrict__ W, __half* __restrict__ hi) {
    int i = blockIdx.x * blockDim.x + threadIdx.x;
    if (i >= 256 * NO) return;
    int k = i / NO, n = i % NO;
    hi[n * 256 + k] = __float2half_rn(W[i]);
}

// ---------------- GEMM: 8 warps, A fp16, B fp16 hi-only, fused alpha --------------
template <int NO>
__global__ __launch_bounds__(256, 2) void k_gemm_mma(const __half* __restrict__ A,
                                                     const __half* __restrict__ Bhi,
                                                     __half* __restrict__ Hhi,
                                                     const float* __restrict__ a_s,
                                                     const float* __restrict__ a_d) {
    constexpr int BM = 128, BN = (NO == 256) ? 128 : 64;
    constexpr int WN = BN / 2;
    constexpr int NG = WN / 8;
    constexpr int ASZ = 128 * 128;
    constexpr int BSZ = BN * 128;
    constexpr int STG = ASZ + BSZ;

    extern __shared__ __align__(1024) char smraw[];
    const uint32_t sb = smem_u32(smraw);
    const int tid = threadIdx.x, w = tid >> 5, lane = tid & 31;
    const int wm = w & 3, wn = w >> 2;
    const int bm = blockIdx.y * BM, bn = blockIdx.x * BN;

    auto load = [&](int c) {
        const uint32_t st = sb + (c & 1) * STG;
        const int ko = c * 64;
        for (int t = tid; t < 128 * 8; t += 256) {
            int r = t >> 3, q = t & 7;
            int gr = bm + r; if (gr >= NN) gr = NN - 1;
            cp_async16(st + SW128(r * 128 + q * 16), A + (size_t)gr * 256 + ko + q * 8);
        }
        for (int t = tid; t < BN * 8; t += 256) {
            int r = t >> 3, q = t & 7;
            cp_async16(st + ASZ + SW128(r * 128 + q * 16),
                       Bhi + (size_t)(bn + r) * 256 + ko + q * 8);
        }
        asm volatile("cp.async.commit_group;" ::: "memory");
    };

    load(0);
    load(1);

    float acc[2][NG][4] = {};
    const int a_row = wm * 32 + (lane & 15);
    const int a_colq = (lane >> 4) * 16;
    const int b_row = wn * WN + (lane >> 4) * 8 + (lane & 7);
    const int b_colq = ((lane >> 3) & 1) * 16;

    for (int c = 0; c < 4; ++c) {
        const uint32_t st = sb + (c & 1) * STG;
        if (c < 3) asm volatile("cp.async.wait_group 1;" ::: "memory");
        else       asm volatile("cp.async.wait_group 0;" ::: "memory");
        __syncthreads();
#pragma unroll
        for (int kk = 0; kk < 4; ++kk) {
            uint32_t ah[8], bb[2 * NG];
#pragma unroll
            for (int f = 0; f < 2; ++f)
                ldsm_x4(ah[f * 4], ah[f * 4 + 1], ah[f * 4 + 2], ah[f * 4 + 3],
                        st + SW128((a_row + f * 16) * 128 + kk * 32 + a_colq));
#pragma unroll
            for (int g2 = 0; g2 < NG / 2; ++g2)
                ldsm_x4(bb[g2 * 4], bb[g2 * 4 + 1], bb[g2 * 4 + 2], bb[g2 * 4 + 3],
                        st + ASZ + SW128((b_row + g2 * 16) * 128 + kk * 32 + b_colq));
#pragma unroll
            for (int f = 0; f < 2; ++f)
#pragma unroll
                for (int g = 0; g < NG; ++g)
                    mma16816(acc[f][g], ah + f * 4, bb + g * 2);
        }
        __syncthreads();
        if (c + 2 < 4) load(c + 2);
    }

    if constexpr (NO == 256) {
        const int head = blockIdx.x * 2 + wn;
        float as_r[2 * NG], ad_r[2 * NG];
#pragma unroll
        for (int g = 0; g < NG; ++g) {
            int cl = head * 64 + g * 8 + (lane & 3) * 2;
            as_r[g * 2] = a_s[cl];     as_r[g * 2 + 1] = a_s[cl + 1];
            ad_r[g * 2] = a_d[cl];     ad_r[g * 2 + 1] = a_d[cl + 1];
        }
#pragma unroll
        for (int f = 0; f < 2; ++f) {
#pragma unroll
            for (int rr = 0; rr < 2; ++rr) {
                float ps = 0.f, pd = 0.f;
#pragma unroll
                for (int g = 0; g < NG; ++g) {
                    float c0 = acc[f][g][rr * 2], c1 = acc[f][g][rr * 2 + 1];
                    ps += c0 * as_r[g * 2] + c1 * as_r[g * 2 + 1];
                    pd += c0 * ad_r[g * 2] + c1 * ad_r[g * 2 + 1];
                }
                ps += __shfl_xor_sync(0xffffffffu, ps, 1);
                ps += __shfl_xor_sync(0xffffffffu, ps, 2);
                pd += __shfl_xor_sync(0xffffffffu, pd, 1);
                pd += __shfl_xor_sync(0xffffffffu, pd, 2);
                int m = bm + wm * 32 + f * 16 + rr * 8 + (lane >> 2);
                if ((lane & 3) == 0 && m < NN) {
                    g_as[m * 4 + head] = ps;
                    g_ad[m * 4 + head] = pd;
                }
            }
        }
#pragma unroll
        for (int f = 0; f < 2; ++f) {
#pragma unroll
            for (int g = 0; g < NG; ++g) {
                int m = bm + wm * 32 + f * 16 + (lane >> 2);
                int n = bn + wn * 64 + g * 8 + (lane & 3) * 2;
#pragma unroll
                for (int rr = 0; rr < 2; ++rr) {
                    int mm = m + rr * 8;
                    if (mm < NN)
                        *(__half2*)(Hhi + (size_t)mm * NO + n) =
                            __floats2half2_rn(acc[f][g][rr * 2], acc[f][g][rr * 2 + 1]);
                }
            }
        }
    } else {
#pragma unroll
        for (int f = 0; f < 2; ++f) {
#pragma unroll
            for (int g = 0; g < NG; ++g) {
                int m = bm + wm * 32 + f * 16 + (lane >> 2);
                int n = bn + wn * WN + g * 8 + (lane & 3) * 2;
#pragma unroll
                for (int rr = 0; rr < 2; ++rr) {
                    int mm = m + rr * 8;
                    if (mm < NN)
                        *(__half2*)(Hhi + (size_t)mm * NO + n) =
                            __floats2half2_rn(acc[f][g][rr * 2], acc[f][g][rr * 2 + 1]);
                }
            }
        }
        // fused alpha (H=1): cross-warp (wn 0/1) reduction via reused tile smem
        float as_r[2 * NG], ad_r[2 * NG];
#pragma unroll
        for (int g = 0; g < NG; ++g) {
            int cl = wn * 32 + g * 8 + (lane & 3) * 2;
            as_r[g * 2] = a_s[cl];     as_r[g * 2 + 1] = a_s[cl + 1];
            ad_r[g * 2] = a_d[cl];     ad_r[g * 2 + 1] = a_d[cl + 1];
        }
        float psv[2][2], pdv[2][2];
#pragma unroll
        for (int f = 0; f < 2; ++f) {
#pragma unroll
            for (int rr = 0; rr < 2; ++rr) {
                float ps = 0.f, pd = 0.f;
#pragma unroll
                for (int g = 0; g < NG; ++g) {
                    float c0 = acc[f][g][rr * 2], c1 = acc[f][g][rr * 2 + 1];
                    ps += c0 * as_r[g * 2] + c1 * as_r[g * 2 + 1];
                    pd += c0 * ad_r[g * 2] + c1 * ad_r[g * 2 + 1];
                }
                ps += __shfl_xor_sync(0xffffffffu, ps, 1);
                ps += __shfl_xor_sync(0xffffffffu, ps, 2);
                pd += __shfl_xor_sync(0xffffffffu, pd, 1);
                pd += __shfl_xor_sync(0xffffffffu, pd, 2);
                psv[f][rr] = ps; pdv[f][rr] = pd;
            }
        }
        float* red = (float*)smraw;
        if (wn == 0 && (lane & 3) == 0) {
#pragma unroll
            for (int f = 0; f < 2; ++f)
#pragma unroll
                for (int rr = 0; rr < 2; ++rr) {
                    int row = wm * 32 + f * 16 + rr * 8 + (lane >> 2);
                    red[row] = psv[f][rr];
                    red[128 + row] = pdv[f][rr];
                }
        }
        __syncthreads();
        if (wn == 1 && (lane & 3) == 0) {
#pragma unroll
            for (int f = 0; f < 2; ++f)
#pragma unroll
                for (int rr = 0; rr < 2; ++rr) {
                    int row = wm * 32 + f * 16 + rr * 8 + (lane >> 2);
                    int m = bm + row;
                    if (m < NN) {
                        g_as[m] = red[row] + psv[f][rr];
                        g_ad[m] = red[128 + row] + pdv[f][rr];
                    }
                }
        }
    }
}

// ---------------- CSR build -------------------------------------------------------
__global__ void k_zero_cnt() {
    int i = blockIdx.x * blockDim.x + threadIdx.x;
    if (i < NN) g_cnt[i] = 0;
}
__global__ void k_count(const int* __restrict__ ei) {
    int e = blockIdx.x * blockDim.x + threadIdx.x;
    if (e >= ET) return;
    int d = (e < EE) ? ei[EE + e] : (e - EE);
    atomicAdd(&g_cnt[d], 1);
}
__global__ void k_scan1() {
    __shared__ int sh[SCAN_B];
    int tid = threadIdx.x;
    int i = blockIdx.x * SCAN_B + tid;
    int v = (i < NN) ? g_cnt[i] : 0;
    sh[tid] = v;
    __syncthreads();
    for (int off = 1; off < SCAN_B; off <<= 1) {
        int t = (tid >= off) ? sh[tid - off] : 0;
        __syncthreads();
        sh[tid] += t;
        __syncthreads();
    }
    g_incl[i] = sh[tid];
    if (tid == SCAN_B - 1) g_bsum[blockIdx.x] = sh[tid];
}
__global__ void k_scan2() {
    if (threadIdx.x == 0) {
        int s = 0;
        for (int i = 0; i < NBLK; ++i) { int t = g_bsum[i]; g_bsum[i] = s; s += t; }
    }
}
__global__ void k_scan3() {
    int i = blockIdx.x * blockDim.x + threadIdx.x;
    if (i < NN) {
        int v = g_cnt[i];
        int ex = g_incl[i] - v + g_bsum[i >> 10];
        g_rowptr[i] = ex;
        g_fill[i] = ex;
    }
    if (i == 0) g_rowptr[NN] = ET;
}
__global__ void k_fill(const int* __restrict__ ei) {
    int e = blockIdx.x * blockDim.x + threadIdx.x;
    if (e >= ET) return;
    int s, d;
    if (e < EE) { s = ei[e]; d = ei[EE + e]; }
    else        { s = e - EE; d = s; }
    int pos = atomicAdd(&g_fill[d], 1);
    g_col[pos] = s;
}

// ---------------- conv H=4: one warp/node; no-max softmax; staged exp weights -----
template <bool RELU>
__global__ __launch_bounds__(256) void k_conv4(const float* __restrict__ as_,
                                               const float* __restrict__ ad_,
                                               const float* __restrict__ bias,
                                               __half* __restrict__ ohi) {
    int warp = (blockIdx.x * blockDim.x + threadIdx.x) >> 5;
    int lane = threadIdx.x & 31;
    if (warp >= NN) return;
    int beg = g_rowptr[warp], end = g_rowptr[warp + 1];

    float adh0 = ad_[warp * 4 + 0], adh1 = ad_[warp * 4 + 1];
    float adh2 = ad_[warp * 4 + 2], adh3 = ad_[warp * 4 + 3];

    float s0 = 0.f, s1 = 0.f, s2 = 0.f, s3 = 0.f;
    for (int i = beg + lane; i < end; i += 32) {
        int s = g_col[i];
        float4 a4 = ((const float4*)as_)[s];
        float e0 = a4.x + adh0; e0 = e0 > 0.f ? e0 : 0.2f * e0;
        float e1 = a4.y + adh1; e1 = e1 > 0.f ? e1 : 0.2f * e1;
        float e2 = a4.z + adh2; e2 = e2 > 0.f ? e2 : 0.2f * e2;
        float e3 = a4.w + adh3; e3 = e3 > 0.f ? e3 : 0.2f * e3;
        float x0 = __expf(e0), x1 = __expf(e1), x2 = __expf(e2), x3 = __expf(e3);
        s0 += x0; s1 += x1; s2 += x2; s3 += x3;
        ((float4*)g_ew)[i] = make_float4(x0, x1, x2, x3);
    }
#pragma unroll
    for (int o = 16; o; o >>= 1) {
        s0 += __shfl_xor_sync(0xffffffffu, s0, o);
        s1 += __shfl_xor_sync(0xffffffffu, s1, o);
        s2 += __shfl_xor_sync(0xffffffffu, s2, o);
        s3 += __shfl_xor_sync(0xffffffffu, s3, o);
    }
    __threadfence_block();
    __syncwarp();

    const int myhead = lane >> 3;
    float smh = myhead == 0 ? s0 : (myhead == 1 ? s1 : (myhead == 2 ? s2 : s3));
    float acc[8] = {};
#pragma unroll 8
    for (int i = beg; i < end; ++i) {
        int s = g_col[i];
        float w = g_ew[(size_t)i * 4 + myhead];
        uint4 raw = *(const uint4*)(g_hhi + (size_t)s * 256 + lane * 8);
        float2 f0 = __half22float2(*(__half2*)&raw.x);
        float2 f1 = __half22float2(*(__half2*)&raw.y);
        float2 f2 = __half22float2(*(__half2*)&raw.z);
        float2 f3 = __half22float2(*(__half2*)&raw.w);
        acc[0] += w * f0.x; acc[1] += w * f0.y; acc[2] += w * f1.x; acc[3] += w * f1.y;
        acc[4] += w * f2.x; acc[5] += w * f2.y; acc[6] += w * f3.x; acc[7] += w * f3.y;
    }
    float scale = 1.f / (smh * (float)(end - beg));
    float v[8];
#pragma unroll
    for (int j = 0; j < 8; ++j) {
        v[j] = acc[j] * scale + bias[lane * 8 + j];
        if (RELU) v[j] = fmaxf(v[j], 0.f);
    }
    __half2 vh[4];
#pragma unroll
    for (int j = 0; j < 4; ++j)
        vh[j] = __floats2half2_rn(v[2 * j], v[2 * j + 1]);
    *(uint4*)(ohi + (size_t)warp * 256 + lane * 8) = *(uint4*)vh;
}

// ---------------- conv H=1 (last layer) -------------------------------------------
__global__ __launch_bounds__(256) void k_conv1(const float* __restrict__ as_,
                                               const float* __restrict__ ad_,
                                               const float* __restrict__ bias,
                                               float* __restrict__ out) {
    int warp = (blockIdx.x * blockDim.x + threadIdx.x) >> 5;
    int lane = threadIdx.x & 31;
    if (warp >= NN) return;
    int beg = g_rowptr[warp], end = g_rowptr[warp + 1];

    float adh = ad_[warp];
    float sm = 0.f;
    for (int i = beg + lane; i < end; i += 32) {
        int s = g_col[i];
        float e = as_[s] + adh;
        e = e > 0.f ? e : 0.2f * e;
        float x = __expf(e);
        sm += x;
        g_ew[i] = x;
    }
#pragma unroll
    for (int o = 16; o; o >>= 1)
        sm += __shfl_xor_sync(0xffffffffu, sm, o);
    __threadfence_block();
    __syncwarp();

    float acc0 = 0.f, acc1 = 0.f;
#pragma unroll 8
    for (int i = beg; i < end; ++i) {
        int s = g_col[i];
        float w = g_ew[i];
        float2 f0 = __half22float2(((const __half2*)(g_hhi + (size_t)s * 64))[lane]);
        acc0 += w * f0.x; acc1 += w * f0.y;
    }
    float scale = 1.f / (sm * (float)(end - beg));
    out[(size_t)warp * 64 + 2 * lane]     = acc0 * scale + bias[2 * lane];
    out[(size_t)warp * 64 + 2 * lane + 1] = acc1 * scale + bias[2 * lane + 1];
}

// ---------------- launch ----------------------------------------------------------
extern "C" void kernel_launch(void* const* d_in, const int* in_sizes, int n_in,
                              void* d_out, int out_size) {
    const float* x   = (const float*)d_in[0];
    const int*   ei  = (const int*)d_in[1];
    const float* W0  = (const float*)d_in[2];
    const float* a0s = (const float*)d_in[3];
    const float* a0d = (const float*)d_in[4];
    const float* b0  = (const float*)d_in[5];
    const float* W1  = (const float*)d_in[6];
    const float* a1s = (const float*)d_in[7];
    const float* a1d = (const float*)d_in[8];
    const float* b1  = (const float*)d_in[9];
    const float* W2  = (const float*)d_in[10];
    const float* a2s = (const float*)d_in[11];
    const float* a2d = (const float*)d_in[12];
    const float* b2  = (const float*)d_in[13];
    float* out = (float*)d_out;

    void* p;
    cudaGetSymbolAddress(&p, g_ahi);  __half* ahi = (__half*)p;
    cudaGetSymbolAddress(&p, g_hhi);  __half* hhi = (__half*)p;
    cudaGetSymbolAddress(&p, g_w0hi); __half* w0hi = (__half*)p;
    cudaGetSymbolAddress(&p, g_w1hi); __half* w1hi = (__half*)p;
    cudaGetSymbolAddress(&p, g_w2hi); __half* w2hi = (__half*)p;
    cudaGetSymbolAddress(&p, g_as);   float* asb = (float*)p;
    cudaGetSymbolAddress(&p, g_ad);   float* adb = (float*)p;

    const int SMEM256 = 2 * (128 * 128 + 128 * 128);  // 65536
    const int SMEM64  = 2 * (128 * 128 + 64 * 128);   // 49152

    static cudaStream_t s2 = nullptr;
    static cudaEvent_t ev_fork, ev_w0, ev_join;
    if (!s2) {
        cudaFuncSetAttribute(k_gemm_mma<256>, cudaFuncAttributeMaxDynamicSharedMemorySize, SMEM256);
        cudaFuncSetAttribute(k_gemm_mma<64>,  cudaFuncAttributeMaxDynamicSharedMemorySize, SMEM64);
        cudaStreamCreateWithFlags(&s2, cudaStreamNonBlocking);
        cudaEventCreateWithFlags(&ev_fork, cudaEventDisableTiming);
        cudaEventCreateWithFlags(&ev_w0,   cudaEventDisableTiming);
        cudaEventCreateWithFlags(&ev_join, cudaEventDisableTiming);
    }

    const int NODE_BLKS = (NN + 7) / 8;
    dim3 g256(2, (NN + 127) / 128);
    dim3 g64(1, (NN + 127) / 128);

    // fork: side stream does W0 convert first, then CSR build + W1/W2 converts
    cudaEventRecord(ev_fork, 0);
    cudaStreamWaitEvent(s2, ev_fork, 0);
    k_wt_hi<256><<<(256 * 256 + 255) / 256, 256, 0, s2>>>(W0, w0hi);
    cudaEventRecord(ev_w0, s2);
    k_zero_cnt<<<(NN + 255) / 256, 256, 0, s2>>>();
    k_count<<<(ET + 255) / 256, 256, 0, s2>>>(ei);
    k_scan1<<<NBLK, SCAN_B, 0, s2>>>();
    k_scan2<<<1, 32, 0, s2>>>();
    k_scan3<<<(NN + 255) / 256, 256, 0, s2>>>();
    k_fill<<<(ET + 255) / 256, 256, 0, s2>>>(ei);
    k_wt_hi<256><<<(256 * 256 + 255) / 256, 256, 0, s2>>>(W1, w1hi);
    k_wt_hi<64><<<(256 * 64 + 255) / 256, 256, 0, s2>>>(W2, w2hi);
    cudaEventRecord(ev_join, s2);

    // main stream: layer-0 GEMM
    k_tofp16_x<<<(NN * 64 + 255) / 256, 256>>>(x);
    cudaStreamWaitEvent(0, ev_w0, 0);
    k_gemm_mma<256><<<g256, 256, SMEM256>>>(ahi, w0hi, hhi, a0s, a0d);

    // join: conv0 needs CSR
    cudaStreamWaitEvent(0, ev_join, 0);
    k_conv4<true><<<NODE_BLKS, 256>>>(asb, adb, b0, ahi);

    // layer 1
    k_gemm_mma<256><<<g256, 256, SMEM256>>>(ahi, w1hi, hhi, a1s, a1d);
    k_conv4<true><<<NODE_BLKS, 256>>>(asb, adb, b1, ahi);

    // layer 2 (heads=1, alpha fused)
    k_gemm_mma<64><<<g64, 256, SMEM64>>>(ahi, w2hi, hhi, a2s, a2d);
    k_conv1<<<NODE_BLKS, 256>>>(asb, adb, b2, out);
}

// round 16
// speedup vs baseline: 1.4306x; 1.0170x over previous
#include <cuda_runtime.h>
#include <cuda_fp16.h>
#include <cstdint>

#define NN 50000
#define EE 600000
#define ET (EE + NN)
#define SCAN_B 1024
#define NBLK ((NN + SCAN_B - 1) / SCAN_B)

// ---------------- scratch ---------------------------------------------------------
__device__ __half g_ahi[(size_t)NN * 256];      // layer input (fp16)
__device__ __half g_hhi[(size_t)NN * 256];      // GEMM output hi
__device__ __half g_w0hi[256 * 256];
__device__ __half g_w1hi[256 * 256];
__device__ __half g_w2hi[64 * 256];
__device__ float g_as[NN * 4];
__device__ float g_ad[NN * 4];
__device__ float g_ew[(size_t)ET * 4];          // per-edge exp weights (4 heads)
__device__ int   g_cnt[NN];
__device__ int   g_incl[NBLK * SCAN_B];
__device__ int   g_bsum[NBLK];
__device__ int   g_rowptr[NN + 1];
__device__ int   g_fill[NN];
__device__ int   g_col[ET];

// ---------------- PTX helpers -----------------------------------------------------
__device__ __forceinline__ uint32_t smem_u32(const void* p) {
    uint32_t a;
    asm("{ .reg .u64 t; cvta.to.shared.u64 t, %1; cvt.u32.u64 %0, t; }" : "=r"(a) : "l"(p));
    return a;
}
__device__ __forceinline__ void cp_async16(uint32_t dst, const void* src) {
    asm volatile("cp.async.cg.shared.global [%0], [%1], 16;"
                 :: "r"(dst), "l"(__cvta_generic_to_global(src)) : "memory");
}
__device__ __forceinline__ void ldsm_x4(uint32_t& r0, uint32_t& r1, uint32_t& r2,
                                        uint32_t& r3, uint32_t addr) {
    asm volatile("ldmatrix.sync.aligned.m8n8.x4.shared.b16 {%0,%1,%2,%3}, [%4];"
                 : "=r"(r0), "=r"(r1), "=r"(r2), "=r"(r3) : "r"(addr));
}
__device__ __forceinline__ void mma16816(float* c, const uint32_t* a, const uint32_t* b) {
    asm volatile("mma.sync.aligned.m16n8k16.row.col.f32.f16.f16.f32 "
                 "{%0,%1,%2,%3}, {%4,%5,%6,%7}, {%8,%9}, {%0,%1,%2,%3};"
                 : "+f"(c[0]), "+f"(c[1]), "+f"(c[2]), "+f"(c[3])
                 : "r"(a[0]), "r"(a[1]), "r"(a[2]), "r"(a[3]), "r"(b[0]), "r"(b[1]));
}
#define SW128(o) ((o) ^ (((o) >> 3) & 0x70))

// ---------------- conversions -----------------------------------------------------
__global__ void k_tofp16_x(const float* __restrict__ x) {
    int i = blockIdx.x * blockDim.x + threadIdx.x;
    if (i >= NN * 64) return;
    float4 v = ((const float4*)x)[i];
    ((__half2*)g_ahi)[2 * i]     = __floats2half2_rn(v.x, v.y);
    ((__half2*)g_ahi)[2 * i + 1] = __floats2half2_rn(v.z, v.w);
}

__global__ void k_wt_hi0(const float* __restrict__ W) {
    int i = blockIdx.x * blockDim.x + threadIdx.x;
    if (i >= 256 * 256) return;
    int k = i / 256, n = i % 256;
    g_w0hi[n * 256 + k] = __float2half_rn(W[i]);
}

// merged W1 + W2 transpose+convert
__global__ void k_wt_hi12(const float* __restrict__ W1, const float* __restrict__ W2) {
    int i = blockIdx.x * blockDim.x + threadIdx.x;
    if (i < 256 * 256) {
        int k = i / 256, n = i % 256;
        g_w1hi[n * 256 + k] = __float2half_rn(W1[i]);
    } else if (i < 256 * 256 + 256 * 64) {
        int j = i - 256 * 256;
        int k = j / 64, n = j % 64;
        g_w2hi[n * 256 + k] = __float2half_rn(W2[j]);
    }
}

// ---------------- GEMM: 8 warps, A fp16, B fp16 hi-only, fused alpha --------------
template <int NO>
__global__ __launch_bounds__(256, 2) void k_gemm_mma(const __half* __restrict__ A,
                                                     const __half* __restrict__ Bhi,
                                                     __half* __restrict__ Hhi,
                                                     const float* __restrict__ a_s,
                                                     const float* __restrict__ a_d) {
    constexpr int BM = 128, BN = (NO == 256) ? 128 : 64;
    constexpr int WN = BN / 2;
    constexpr int NG = WN / 8;
    constexpr int ASZ = 128 * 128;
    constexpr int BSZ = BN * 128;
    constexpr int STG = ASZ + BSZ;

    extern __shared__ __align__(1024) char smraw[];
    const uint32_t sb = smem_u32(smraw);
    const int tid = threadIdx.x, w = tid >> 5, lane = tid & 31;
    const int wm = w & 3, wn = w >> 2;
    const int bm = blockIdx.y * BM, bn = blockIdx.x * BN;

    auto load = [&](int c) {
        const uint32_t st = sb + (c & 1) * STG;
        const int ko = c * 64;
        for (int t = tid; t < 128 * 8; t += 256) {
            int r = t >> 3, q = t & 7;
            int gr = bm + r; if (gr >= NN) gr = NN - 1;
            cp_async16(st + SW128(r * 128 + q * 16), A + (size_t)gr * 256 + ko + q * 8);
        }
        for (int t = tid; t < BN * 8; t += 256) {
            int r = t >> 3, q = t & 7;
            cp_async16(st + ASZ + SW128(r * 128 + q * 16),
                       Bhi + (size_t)(bn + r) * 256 + ko + q * 8);
        }
        asm volatile("cp.async.commit_group;" ::: "memory");
    };

    load(0);
    load(1);

    float acc[2][NG][4] = {};
    const int a_row = wm * 32 + (lane & 15);
    const int a_colq = (lane >> 4) * 16;
    const int b_row = wn * WN + (lane >> 4) * 8 + (lane & 7);
    const int b_colq = ((lane >> 3) & 1) * 16;

    for (int c = 0; c < 4; ++c) {
        const uint32_t st = sb + (c & 1) * STG;
        if (c < 3) asm volatile("cp.async.wait_group 1;" ::: "memory");
        else       asm volatile("cp.async.wait_group 0;" ::: "memory");
        __syncthreads();
#pragma unroll
        for (int kk = 0; kk < 4; ++kk) {
            uint32_t ah[8], bb[2 * NG];
#pragma unroll
            for (int f = 0; f < 2; ++f)
                ldsm_x4(ah[f * 4], ah[f * 4 + 1], ah[f * 4 + 2], ah[f * 4 + 3],
                        st + SW128((a_row + f * 16) * 128 + kk * 32 + a_colq));
#pragma unroll
            for (int g2 = 0; g2 < NG / 2; ++g2)
                ldsm_x4(bb[g2 * 4], bb[g2 * 4 + 1], bb[g2 * 4 + 2], bb[g2 * 4 + 3],
                        st + ASZ + SW128((b_row + g2 * 16) * 128 + kk * 32 + b_colq));
#pragma unroll
            for (int f = 0; f < 2; ++f)
#pragma unroll
                for (int g = 0; g < NG; ++g)
                    mma16816(acc[f][g], ah + f * 4, bb + g * 2);
        }
        __syncthreads();
        if (c + 2 < 4) load(c + 2);
    }

    if constexpr (NO == 256) {
        const int head = blockIdx.x * 2 + wn;
        float as_r[2 * NG], ad_r[2 * NG];
#pragma unroll
        for (int g = 0; g < NG; ++g) {
            int cl = head * 64 + g * 8 + (lane & 3) * 2;
            as_r[g * 2] = a_s[cl];     as_r[g * 2 + 1] = a_s[cl + 1];
            ad_r[g * 2] = a_d[cl];     ad_r[g * 2 + 1] = a_d[cl + 1];
        }
#pragma unroll
        for (int f = 0; f < 2; ++f) {
#pragma unroll
            for (int rr = 0; rr < 2; ++rr) {
                float ps = 0.f, pd = 0.f;
#pragma unroll
                for (int g = 0; g < NG; ++g) {
                    float c0 = acc[f][g][rr * 2], c1 = acc[f][g][rr * 2 + 1];
                    ps += c0 * as_r[g * 2] + c1 * as_r[g * 2 + 1];
                    pd += c0 * ad_r[g * 2] + c1 * ad_r[g * 2 + 1];
                }
                ps += __shfl_xor_sync(0xffffffffu, ps, 1);
                ps += __shfl_xor_sync(0xffffffffu, ps, 2);
                pd += __shfl_xor_sync(0xffffffffu, pd, 1);
                pd += __shfl_xor_sync(0xffffffffu, pd, 2);
                int m = bm + wm * 32 + f * 16 + rr * 8 + (lane >> 2);
                if ((lane & 3) == 0 && m < NN) {
                    g_as[m * 4 + head] = ps;
                    g_ad[m * 4 + head] = pd;
                }
            }
        }
#pragma unroll
        for (int f = 0; f < 2; ++f) {
#pragma unroll
            for (int g = 0; g < NG; ++g) {
                int m = bm + wm * 32 + f * 16 + (lane >> 2);
                int n = bn + wn * 64 + g * 8 + (lane & 3) * 2;
#pragma unroll
                for (int rr = 0; rr < 2; ++rr) {
                    int mm = m + rr * 8;
                    if (mm < NN)
                        *(__half2*)(Hhi + (size_t)mm * NO + n) =
                            __floats2half2_rn(acc[f][g][rr * 2], acc[f][g][rr * 2 + 1]);
                }
            }
        }
    } else {
#pragma unroll
        for (int f = 0; f < 2; ++f) {
#pragma unroll
            for (int g = 0; g < NG; ++g) {
                int m = bm + wm * 32 + f * 16 + (lane >> 2);
                int n = bn + wn * WN + g * 8 + (lane & 3) * 2;
#pragma unroll
                for (int rr = 0; rr < 2; ++rr) {
                    int mm = m + rr * 8;
                    if (mm < NN)
                        *(__half2*)(Hhi + (size_t)mm * NO + n) =
                            __floats2half2_rn(acc[f][g][rr * 2], acc[f][g][rr * 2 + 1]);
                }
            }
        }
        // fused alpha (H=1): cross-warp (wn 0/1) reduction via reused tile smem
        float as_r[2 * NG], ad_r[2 * NG];
#pragma unroll
        for (int g = 0; g < NG; ++g) {
            int cl = wn * 32 + g * 8 + (lane & 3) * 2;
            as_r[g * 2] = a_s[cl];     as_r[g * 2 + 1] = a_s[cl + 1];
            ad_r[g * 2] = a_d[cl];     ad_r[g * 2 + 1] = a_d[cl + 1];
        }
        float psv[2][2], pdv[2][2];
#pragma unroll
        for (int f = 0; f < 2; ++f) {
#pragma unroll
            for (int rr = 0; rr < 2; ++rr) {
                float ps = 0.f, pd = 0.f;
#pragma unroll
                for (int g = 0; g < NG; ++g) {
                    float c0 = acc[f][g][rr * 2], c1 = acc[f][g][rr * 2 + 1];
                    ps += c0 * as_r[g * 2] + c1 * as_r[g * 2 + 1];
                    pd += c0 * ad_r[g * 2] + c1 * ad_r[g * 2 + 1];
                }
                ps += __shfl_xor_sync(0xffffffffu, ps, 1);
                ps += __shfl_xor_sync(0xffffffffu, ps, 2);
                pd += __shfl_xor_sync(0xffffffffu, pd, 1);
                pd += __shfl_xor_sync(0xffffffffu, pd, 2);
                psv[f][rr] = ps; pdv[f][rr] = pd;
            }
        }
        float* red = (float*)smraw;
        if (wn == 0 && (lane & 3) == 0) {
#pragma unroll
            for (int f = 0; f < 2; ++f)
#pragma unroll
                for (int rr = 0; rr < 2; ++rr) {
                    int row = wm * 32 + f * 16 + rr * 8 + (lane >> 2);
                    red[row] = psv[f][rr];
                    red[128 + row] = pdv[f][rr];
                }
        }
        __syncthreads();
        if (wn == 1 && (lane & 3) == 0) {
#pragma unroll
            for (int f = 0; f < 2; ++f)
#pragma unroll
                for (int rr = 0; rr < 2; ++rr) {
                    int row = wm * 32 + f * 16 + rr * 8 + (lane >> 2);
                    int m = bm + row;
                    if (m < NN) {
                        g_as[m] = red[row] + psv[f][rr];
                        g_ad[m] = red[128 + row] + pdv[f][rr];
                    }
                }
        }
    }
}

// ---------------- CSR build -------------------------------------------------------
__global__ void k_count(const int* __restrict__ ei) {
    int e = blockIdx.x * blockDim.x + threadIdx.x;
    if (e >= ET) return;
    int d = (e < EE) ? ei[EE + e] : (e - EE);
    atomicAdd(&g_cnt[d], 1);
}
__global__ void k_scan1() {
    __shared__ int sh[SCAN_B];
    int tid = threadIdx.x;
    int i = blockIdx.x * SCAN_B + tid;
    int v = (i < NN) ? g_cnt[i] : 0;
    sh[tid] = v;
    __syncthreads();
    for (int off = 1; off < SCAN_B; off <<= 1) {
        int t = (tid >= off) ? sh[tid - off] : 0;
        __syncthreads();
        sh[tid] += t;
        __syncthreads();
    }
    g_incl[i] = sh[tid];
    if (tid == SCAN_B - 1) g_bsum[blockIdx.x] = sh[tid];
}
// scan3 with fused block-offset scan (replaces scan2+scan3)
__global__ void k_scan3() {
    __shared__ int base_sh;
    int b = blockIdx.x;
    if (threadIdx.x < 32) {
        int v = 0;
        for (int j = (int)threadIdx.x; j < b; j += 32) v += g_bsum[j];
#pragma unroll
        for (int o = 16; o; o >>= 1) v += __shfl_xor_sync(0xffffffffu, v, o);
        if (threadIdx.x == 0) base_sh = v;
    }
    __syncthreads();
    int base = base_sh;
    int i = b * SCAN_B + threadIdx.x;
    if (i < NN) {
        int v = g_cnt[i];
        int ex = g_incl[i] - v + base;
        g_rowptr[i] = ex;
        g_fill[i] = ex;
    }
    if (i == 0) g_rowptr[NN] = ET;
}
__global__ void k_fill(const int* __restrict__ ei) {
    int e = blockIdx.x * blockDim.x + threadIdx.x;
    if (e >= ET) return;
    int s, d;
    if (e < EE) { s = ei[e]; d = ei[EE + e]; }
    else        { s = e - EE; d = s; }
    int pos = atomicAdd(&g_fill[d], 1);
    g_col[pos] = s;
}

// ---------------- conv H=4: one warp/node; no-max softmax; staged exp weights -----
template <bool RELU>
__global__ __launch_bounds__(256) void k_conv4(const float* __restrict__ as_,
                                               const float* __restrict__ ad_,
                                               const float* __restrict__ bias,
                                               __half* __restrict__ ohi) {
    int warp = (blockIdx.x * blockDim.x + threadIdx.x) >> 5;
    int lane = threadIdx.x & 31;
    if (warp >= NN) return;
    int beg = g_rowptr[warp], end = g_rowptr[warp + 1];

    float adh0 = ad_[warp * 4 + 0], adh1 = ad_[warp * 4 + 1];
    float adh2 = ad_[warp * 4 + 2], adh3 = ad_[warp * 4 + 3];

    float s0 = 0.f, s1 = 0.f, s2 = 0.f, s3 = 0.f;
    for (int i = beg + lane; i < end; i += 32) {
        int s = g_col[i];
        float4 a4 = ((const float4*)as_)[s];
        float e0 = a4.x + adh0; e0 = e0 > 0.f ? e0 : 0.2f * e0;
        float e1 = a4.y + adh1; e1 = e1 > 0.f ? e1 : 0.2f * e1;
        float e2 = a4.z + adh2; e2 = e2 > 0.f ? e2 : 0.2f * e2;
        float e3 = a4.w + adh3; e3 = e3 > 0.f ? e3 : 0.2f * e3;
        float x0 = __expf(e0), x1 = __expf(e1), x2 = __expf(e2), x3 = __expf(e3);
        s0 += x0; s1 += x1; s2 += x2; s3 += x3;
        ((float4*)g_ew)[i] = make_float4(x0, x1, x2, x3);
    }
#pragma unroll
    for (int o = 16; o; o >>= 1) {
        s0 += __shfl_xor_sync(0xffffffffu, s0, o);
        s1 += __shfl_xor_sync(0xffffffffu, s1, o);
        s2 += __shfl_xor_sync(0xffffffffu, s2, o);
        s3 += __shfl_xor_sync(0xffffffffu, s3, o);
    }
    __threadfence_block();
    __syncwarp();

    const int myhead = lane >> 3;
    float smh = myhead == 0 ? s0 : (myhead == 1 ? s1 : (myhead == 2 ? s2 : s3));
    float acc[8] = {};
#pragma unroll 8
    for (int i = beg; i < end; ++i) {
        int s = g_col[i];
        float w = g_ew[(size_t)i * 4 + myhead];
        uint4 raw = *(const uint4*)(g_hhi + (size_t)s * 256 + lane * 8);
        float2 f0 = __half22float2(*(__half2*)&raw.x);
        float2 f1 = __half22float2(*(__half2*)&raw.y);
        float2 f2 = __half22float2(*(__half2*)&raw.z);
        float2 f3 = __half22float2(*(__half2*)&raw.w);
        acc[0] += w * f0.x; acc[1] += w * f0.y; acc[2] += w * f1.x; acc[3] += w * f1.y;
        acc[4] += w * f2.x; acc[5] += w * f2.y; acc[6] += w * f3.x; acc[7] += w * f3.y;
    }
    float scale = 1.f / (smh * (float)(end - beg));
    float v[8];
#pragma unroll
    for (int j = 0; j < 8; ++j) {
        v[j] = acc[j] * scale + bias[lane * 8 + j];
        if (RELU) v[j] = fmaxf(v[j], 0.f);
    }
    __half2 vh[4];
#pragma unroll
    for (int j = 0; j < 4; ++j)
        vh[j] = __floats2half2_rn(v[2 * j], v[2 * j + 1]);
    *(uint4*)(ohi + (size_t)warp * 256 + lane * 8) = *(uint4*)vh;
}

// ---------------- conv H=1 (last layer) -------------------------------------------
__global__ __launch_bounds__(256) void k_conv1(const float* __restrict__ as_,
                                               const float* __restrict__ ad_,
                                               const float* __restrict__ bias,
                                               float* __restrict__ out) {
    int warp = (blockIdx.x * blockDim.x + threadIdx.x) >> 5;
    int lane = threadIdx.x & 31;
    if (warp >= NN) return;
    int beg = g_rowptr[warp], end = g_rowptr[warp + 1];

    float adh = ad_[warp];
    float sm = 0.f;
    for (int i = beg + lane; i < end; i += 32) {
        int s = g_col[i];
        float e = as_[s] + adh;
        e = e > 0.f ? e : 0.2f * e;
        float x = __expf(e);
        sm += x;
        g_ew[i] = x;
    }
#pragma unroll
    for (int o = 16; o; o >>= 1)
        sm += __shfl_xor_sync(0xffffffffu, sm, o);
    __threadfence_block();
    __syncwarp();

    float acc0 = 0.f, acc1 = 0.f;
#pragma unroll 8
    for (int i = beg; i < end; ++i) {
        int s = g_col[i];
        float w = g_ew[i];
        float2 f0 = __half22float2(((const __half2*)(g_hhi + (size_t)s * 64))[lane]);
        acc0 += w * f0.x; acc1 += w * f0.y;
    }
    float scale = 1.f / (sm * (float)(end - beg));
    out[(size_t)warp * 64 + 2 * lane]     = acc0 * scale + bias[2 * lane];
    out[(size_t)warp * 64 + 2 * lane + 1] = acc1 * scale + bias[2 * lane + 1];
}

// ---------------- launch ----------------------------------------------------------
extern "C" void kernel_launch(void* const* d_in, const int* in_sizes, int n_in,
                              void* d_out, int out_size) {
    const float* x   = (const float*)d_in[0];
    const int*   ei  = (const int*)d_in[1];
    const float* W0  = (const float*)d_in[2];
    const float* a0s = (const float*)d_in[3];
    const float* a0d = (const float*)d_in[4];
    const float* b0  = (const float*)d_in[5];
    const float* W1  = (const float*)d_in[6];
    const float* a1s = (const float*)d_in[7];
    const float* a1d = (const float*)d_in[8];
    const float* b1  = (const float*)d_in[9];
    const float* W2  = (const float*)d_in[10];
    const float* a2s = (const float*)d_in[11];
    const float* a2d = (const float*)d_in[12];
    const float* b2  = (const float*)d_in[13];
    float* out = (float*)d_out;

    void* p;
    cudaGetSymbolAddress(&p, g_ahi);  __half* ahi = (__half*)p;
    cudaGetSymbolAddress(&p, g_hhi);  __half* hhi = (__half*)p;
    cudaGetSymbolAddress(&p, g_w0hi); __half* w0hi = (__half*)p;
    cudaGetSymbolAddress(&p, g_w1hi); __half* w1hi = (__half*)p;
    cudaGetSymbolAddress(&p, g_w2hi); __half* w2hi = (__half*)p;
    cudaGetSymbolAddress(&p, g_as);   float* asb = (float*)p;
    cudaGetSymbolAddress(&p, g_ad);   float* adb = (float*)p;
    void* cntp;
    cudaGetSymbolAddress(&cntp, g_cnt);

    const int SMEM256 = 2 * (128 * 128 + 128 * 128);  // 65536
    const int SMEM64  = 2 * (128 * 128 + 64 * 128);   // 49152

    static cudaStream_t s2 = nullptr;
    static cudaEvent_t ev_fork, ev_w0, ev_csr, ev_wts;
    if (!s2) {
        cudaFuncSetAttribute(k_gemm_mma<256>, cudaFuncAttributeMaxDynamicSharedMemorySize, SMEM256);
        cudaFuncSetAttribute(k_gemm_mma<64>,  cudaFuncAttributeMaxDynamicSharedMemorySize, SMEM64);
        cudaStreamCreateWithFlags(&s2, cudaStreamNonBlocking);
        cudaEventCreateWithFlags(&ev_fork, cudaEventDisableTiming);
        cudaEventCreateWithFlags(&ev_w0,   cudaEventDisableTiming);
        cudaEventCreateWithFlags(&ev_csr,  cudaEventDisableTiming);
        cudaEventCreateWithFlags(&ev_wts,  cudaEventDisableTiming);
    }

    const int NODE_BLKS = (NN + 7) / 8;
    dim3 g256(2, (NN + 127) / 128);
    dim3 g64(1, (NN + 127) / 128);

    // fork: side stream: W0 convert, CSR build (memset+count+scan1+scan3+fill), W1/W2
    cudaEventRecord(ev_fork, 0);
    cudaStreamWaitEvent(s2, ev_fork, 0);
    k_wt_hi0<<<(256 * 256 + 255) / 256, 256, 0, s2>>>(W0);
    cudaEventRecord(ev_w0, s2);
    cudaMemsetAsync(cntp, 0, NN * sizeof(int), s2);
    k_count<<<(ET + 255) / 256, 256, 0, s2>>>(ei);
    k_scan1<<<NBLK, SCAN_B, 0, s2>>>();
    k_scan3<<<NBLK, SCAN_B, 0, s2>>>();
    k_fill<<<(ET + 255) / 256, 256, 0, s2>>>(ei);
    cudaEventRecord(ev_csr, s2);
    k_wt_hi12<<<(256 * 256 + 256 * 64 + 255) / 256, 256, 0, s2>>>(W1, W2);
    cudaEventRecord(ev_wts, s2);

    // main stream: layer-0 GEMM
    k_tofp16_x<<<(NN * 64 + 255) / 256, 256>>>(x);
    cudaStreamWaitEvent(0, ev_w0, 0);
    k_gemm_mma<256><<<g256, 256, SMEM256>>>(ahi, w0hi, hhi, a0s, a0d);

    // conv0 needs only CSR
    cudaStreamWaitEvent(0, ev_csr, 0);
    k_conv4<true><<<NODE_BLKS, 256>>>(asb, adb, b0, ahi);

    // layer 1 (needs W1 convert)
    cudaStreamWaitEvent(0, ev_wts, 0);
    k_gemm_mma<256><<<g256, 256, SMEM256>>>(ahi, w1hi, hhi, a1s, a1d);
    k_conv4<true><<<NODE_BLKS, 256>>>(asb, adb, b1, ahi);

    // layer 2 (heads=1, alpha fused)
    k_gemm_mma<64><<<g64, 256, SMEM64>>>(ahi, w2hi, hhi, a2s, a2d);
    k_conv1<<<NODE_BLKS, 256>>>(asb, adb, b2, out);
}